// round 1
// baseline (speedup 1.0000x reference)
#include <cuda_runtime.h>
#include <math.h>
#include <stdint.h>

#define NNODES 16384
#define NEDGES 98304
#define NCAND  1024

// ---------------- scratch (static device globals; no allocation) ----------------
__device__ float g_x1[NNODES * 512];     // layer0 output
__device__ float g_x2[NNODES * 1024];    // layer1 output
__device__ float g_x3[NNODES * 64];      // layer2 output
__device__ float g_proj[NNODES * 1024];  // per-layer projection (max nh*fo = 1024)
__device__ float g_skip[NNODES * 1024];  // per-layer skip projection
__device__ float g_ssrc[NNODES * 8];
__device__ float g_stgt[NNODES * 8];
__device__ int   g_cnt[NNODES];
__device__ int   g_off[NNODES + 1];
__device__ int   g_cur[NNODES];
__device__ int   g_srcs[NEDGES];         // src node of each edge, sorted by tgt

// ---------------- CSR build ----------------
__global__ void zero_cnt_kernel() {
    int i = blockIdx.x * blockDim.x + threadIdx.x;
    if (i < NNODES) g_cnt[i] = 0;
}

__global__ void count_kernel(const int* __restrict__ tgt) {
    int e = blockIdx.x * blockDim.x + threadIdx.x;
    if (e < NEDGES) atomicAdd(&g_cnt[tgt[e]], 1);
}

// single block, 1024 threads: exclusive scan of g_cnt -> g_off, also init g_cur
__global__ void scan_kernel() {
    __shared__ int part[1024];
    const int PER = NNODES / 1024;  // 16
    int tid = threadIdx.x;
    int base = tid * PER;
    int local[PER];
    int s = 0;
#pragma unroll
    for (int i = 0; i < PER; i++) { local[i] = g_cnt[base + i]; s += local[i]; }
    part[tid] = s;
    __syncthreads();
    // Hillis-Steele inclusive scan
    for (int d = 1; d < 1024; d <<= 1) {
        int v = (tid >= d) ? part[tid - d] : 0;
        __syncthreads();
        part[tid] += v;
        __syncthreads();
    }
    int run = (tid == 0) ? 0 : part[tid - 1];
#pragma unroll
    for (int i = 0; i < PER; i++) {
        g_off[base + i] = run;
        g_cur[base + i] = run;
        run += local[i];
    }
    if (tid == 1023) g_off[NNODES] = run;
}

__global__ void scatter_kernel(const int* __restrict__ src, const int* __restrict__ tgt) {
    int e = blockIdx.x * blockDim.x + threadIdx.x;
    if (e < NEDGES) {
        int p = atomicAdd(&g_cur[tgt[e]], 1);
        g_srcs[p] = src[e];
    }
}

// ---------------- layer 0 projection (K = 3) ----------------
__global__ void layer0_proj_kernel(const float* __restrict__ fea,
                                   const float* __restrict__ W,
                                   const float* __restrict__ S,
                                   float* __restrict__ proj,
                                   float* __restrict__ skip) {
    int n = blockIdx.x;
    float f0 = fea[n * 3 + 0], f1 = fea[n * 3 + 1], f2 = fea[n * 3 + 2];
    for (int m = threadIdx.x; m < 512; m += blockDim.x) {
        proj[n * 512 + m] = f0 * W[m] + f1 * W[512 + m] + f2 * W[1024 + m];
        skip[n * 512 + m] = f0 * S[m] + f1 * S[512 + m] + f2 * S[1024 + m];
    }
}

// ---------------- generic fp32 tiled GEMM: C[N,M] = A[N,K] @ B[K,M] ----------------
// requires N%BM==0, M%BN==0, K%BK==0, BK%4==0
template <int BM, int BN, int BK, int TM, int TN>
__global__ void gemm_kernel(const float* __restrict__ A, const float* __restrict__ B,
                            float* __restrict__ C, int N, int K, int M) {
    __shared__ float As[BK][BM];
    __shared__ float Bs[BK][BN];
    constexpr int TX = BN / TN;
    constexpr int TY = BM / TM;
    constexpr int NT = TX * TY;
    int tid = threadIdx.x;
    int tx = tid % TX, ty = tid / TX;
    int row0 = blockIdx.y * BM;
    int col0 = blockIdx.x * BN;

    float acc[TM][TN];
#pragma unroll
    for (int i = 0; i < TM; i++)
#pragma unroll
        for (int j = 0; j < TN; j++) acc[i][j] = 0.f;

    for (int k0 = 0; k0 < K; k0 += BK) {
        constexpr int A4 = BM * BK / 4;
        for (int i = tid; i < A4; i += NT) {
            int r  = i / (BK / 4);
            int c4 = (i % (BK / 4)) * 4;
            float4 v = *reinterpret_cast<const float4*>(&A[(size_t)(row0 + r) * K + k0 + c4]);
            As[c4 + 0][r] = v.x; As[c4 + 1][r] = v.y;
            As[c4 + 2][r] = v.z; As[c4 + 3][r] = v.w;
        }
        constexpr int B4 = BK * BN / 4;
        for (int i = tid; i < B4; i += NT) {
            int r  = i / (BN / 4);
            int c4 = (i % (BN / 4)) * 4;
            *reinterpret_cast<float4*>(&Bs[r][c4]) =
                *reinterpret_cast<const float4*>(&B[(size_t)(k0 + r) * M + col0 + c4]);
        }
        __syncthreads();
#pragma unroll
        for (int k = 0; k < BK; k++) {
            float a[TM], b[TN];
#pragma unroll
            for (int i = 0; i < TM; i++) a[i] = As[k][ty * TM + i];
#pragma unroll
            for (int j = 0; j < TN; j++) b[j] = Bs[k][tx * TN + j];
#pragma unroll
            for (int i = 0; i < TM; i++)
#pragma unroll
                for (int j = 0; j < TN; j++) acc[i][j] += a[i] * b[j];
        }
        __syncthreads();
    }
#pragma unroll
    for (int i = 0; i < TM; i++)
#pragma unroll
        for (int j = 0; j < TN; j++)
            C[(size_t)(row0 + ty * TM + i) * M + col0 + tx * TN + j] = acc[i][j];
}

// ---------------- attention scores: s_src/s_tgt [N, nh] ----------------
__global__ void scores_kernel(const float* __restrict__ proj,
                              const float* __restrict__ a_src,
                              const float* __restrict__ a_tgt,
                              float* __restrict__ ssrc, float* __restrict__ stgt,
                              int nh, int fo) {
    int gw = (blockIdx.x * blockDim.x + threadIdx.x) >> 5;
    int lane = threadIdx.x & 31;
    int total = NNODES * nh;
    if (gw >= total) return;
    int n = gw / nh, h = gw % nh;
    const float* p = proj + (size_t)n * nh * fo + h * fo;
    float as_ = 0.f, at_ = 0.f;
    for (int f = lane; f < fo; f += 32) {
        float v = p[f];
        as_ += v * a_src[h * fo + f];
        at_ += v * a_tgt[h * fo + f];
    }
#pragma unroll
    for (int o = 16; o; o >>= 1) {
        as_ += __shfl_down_sync(0xffffffffu, as_, o);
        at_ += __shfl_down_sync(0xffffffffu, at_, o);
    }
    if (lane == 0) { ssrc[n * nh + h] = as_; stgt[n * nh + h] = at_; }
}

// ---------------- softmax-aggregate + skip + bias + activation ----------------
// grid (NNODES, nh), block = fo threads
__global__ void agg_kernel(const float* __restrict__ proj,
                           const float* __restrict__ ssrc,
                           const float* __restrict__ stgt,
                           const float* __restrict__ skip,
                           const float* __restrict__ bias,
                           float* __restrict__ out,
                           int nh, int fo, int act) {
    int n = blockIdx.x, h = blockIdx.y;
    int tid = threadIdx.x;
    int beg = g_off[n], end = g_off[n + 1];
    float st = stgt[n * nh + h];
    __shared__ float red[128];

    // phase 1: max
    float m = -1e30f;
    for (int j = beg + tid; j < end; j += blockDim.x) {
        float e = ssrc[g_srcs[j] * nh + h] + st;
        e = (e < 0.f) ? 0.2f * e : e;
        m = fmaxf(m, e);
    }
    red[tid] = m;
    __syncthreads();
    for (int s = blockDim.x >> 1; s; s >>= 1) {
        if (tid < s) red[tid] = fmaxf(red[tid], red[tid + s]);
        __syncthreads();
    }
    m = red[0];
    __syncthreads();

    // phase 2: sum of exp
    float ssum = 0.f;
    for (int j = beg + tid; j < end; j += blockDim.x) {
        float e = ssrc[g_srcs[j] * nh + h] + st;
        e = (e < 0.f) ? 0.2f * e : e;
        ssum += expf(e - m);
    }
    red[tid] = ssum;
    __syncthreads();
    for (int s = blockDim.x >> 1; s; s >>= 1) {
        if (tid < s) red[tid] += red[tid + s];
        __syncthreads();
    }
    float inv = 1.f / (red[0] + 1e-16f);
    __syncthreads();

    // phase 3: weighted gather
    float acc = 0.f;
    for (int j = beg; j < end; j++) {
        int s_ = g_srcs[j];
        float e = ssrc[s_ * nh + h] + st;
        e = (e < 0.f) ? 0.2f * e : e;
        float alpha = expf(e - m) * inv;
        acc += alpha * proj[(size_t)s_ * nh * fo + h * fo + tid];
    }
    size_t idx = (size_t)n * nh * fo + h * fo + tid;
    float v = acc + skip[idx] + bias[h * fo + tid];
    if (act) v = (v > 0.f) ? v : expm1f(v);
    out[idx] = v;
}

// ---------------- MLP head: 64 -> tanh 256 -> tanh 256 -> 1 ----------------
__global__ void mlp_kernel(const float* __restrict__ x3, const int* __restrict__ cand,
                           const float* __restrict__ mW1, const float* __restrict__ mb1,
                           const float* __restrict__ mW2, const float* __restrict__ mb2,
                           const float* __restrict__ mW3, const float* __restrict__ mb3,
                           float* __restrict__ out, int out_size) {
    int c = blockIdx.x;
    int tid = threadIdx.x;  // 256 threads
    __shared__ float sc[64];
    __shared__ float sh[256];
    int cid = cand[c];
    if (tid < 64) sc[tid] = x3[cid * 64 + tid];
    __syncthreads();

    float acc = mb1[tid];
#pragma unroll 8
    for (int k = 0; k < 64; k++) acc += sc[k] * mW1[k * 256 + tid];
    float h1 = tanhf(acc);
    sh[tid] = h1;
    __syncthreads();

    acc = mb2[tid];
#pragma unroll 8
    for (int k = 0; k < 256; k++) acc += sh[k] * mW2[k * 256 + tid];
    float h2 = tanhf(acc);
    __syncthreads();

    sh[tid] = h2 * mW3[tid];
    __syncthreads();
    for (int s = 128; s; s >>= 1) {
        if (tid < s) sh[tid] += sh[tid + s];
        __syncthreads();
    }
    if (tid == 0) out[c] = sh[0] + mb3[0];
    // second output of the reference is candidates_id; cover the flattened case
    if (out_size > NCAND && tid == 1 && (NCAND + c) < out_size) {
        out[NCAND + c] = (float)cid;
    }
}

// ---------------- launch ----------------
extern "C" void kernel_launch(void* const* d_in, const int* in_sizes, int n_in,
                              void* d_out, int out_size) {
    const float* fea  = (const float*)d_in[0];
    const int*   ei   = (const int*)d_in[1];
    const int*   cand = (const int*)d_in[2];
    const float* W0 = (const float*)d_in[3];
    const float* a_src0 = (const float*)d_in[4];
    const float* a_tgt0 = (const float*)d_in[5];
    const float* b0 = (const float*)d_in[6];
    const float* skip0 = (const float*)d_in[7];
    const float* W1 = (const float*)d_in[8];
    const float* a_src1 = (const float*)d_in[9];
    const float* a_tgt1 = (const float*)d_in[10];
    const float* b1 = (const float*)d_in[11];
    const float* skip1 = (const float*)d_in[12];
    const float* W2 = (const float*)d_in[13];
    const float* a_src2 = (const float*)d_in[14];
    const float* a_tgt2 = (const float*)d_in[15];
    const float* b2 = (const float*)d_in[16];
    const float* skip2 = (const float*)d_in[17];
    const float* mW1 = (const float*)d_in[18];
    const float* mb1 = (const float*)d_in[19];
    const float* mW2 = (const float*)d_in[20];
    const float* mb2 = (const float*)d_in[21];
    const float* mW3 = (const float*)d_in[22];
    const float* mb3 = (const float*)d_in[23];

    const int E = in_sizes[1] / 2;
    const int* src = ei;
    const int* tgt = ei + E;

    float *x1, *x2, *x3, *proj, *skip, *ssrc, *stgt;
    cudaGetSymbolAddress((void**)&x1,   g_x1);
    cudaGetSymbolAddress((void**)&x2,   g_x2);
    cudaGetSymbolAddress((void**)&x3,   g_x3);
    cudaGetSymbolAddress((void**)&proj, g_proj);
    cudaGetSymbolAddress((void**)&skip, g_skip);
    cudaGetSymbolAddress((void**)&ssrc, g_ssrc);
    cudaGetSymbolAddress((void**)&stgt, g_stgt);

    // ---- CSR build (by target) ----
    zero_cnt_kernel<<<(NNODES + 255) / 256, 256>>>();
    count_kernel<<<(NEDGES + 255) / 256, 256>>>(tgt);
    scan_kernel<<<1, 1024>>>();
    scatter_kernel<<<(NEDGES + 255) / 256, 256>>>(src, tgt);

    // ---- layer 0: nh=8, fo=64, concat, elu ----
    layer0_proj_kernel<<<NNODES, 128>>>(fea, W0, skip0, proj, skip);
    {
        int nh = 8, fo = 64;
        int nwarp = NNODES * nh;
        scores_kernel<<<(nwarp * 32 + 255) / 256, 256>>>(proj, a_src0, a_tgt0, ssrc, stgt, nh, fo);
        agg_kernel<<<dim3(NNODES, nh), fo>>>(proj, ssrc, stgt, skip, b0, x1, nh, fo, 1);
    }

    // ---- layer 1: nh=8, fo=128, concat, elu ----
    {
        gemm_kernel<128, 128, 8, 8, 8><<<dim3(1024 / 128, NNODES / 128), 256>>>(x1, W1, proj, NNODES, 512, 1024);
        gemm_kernel<128, 128, 8, 8, 8><<<dim3(1024 / 128, NNODES / 128), 256>>>(x1, skip1, skip, NNODES, 512, 1024);
        int nh = 8, fo = 128;
        int nwarp = NNODES * nh;
        scores_kernel<<<(nwarp * 32 + 255) / 256, 256>>>(proj, a_src1, a_tgt1, ssrc, stgt, nh, fo);
        agg_kernel<<<dim3(NNODES, nh), fo>>>(proj, ssrc, stgt, skip, b1, x2, nh, fo, 1);
    }

    // ---- layer 2: nh=1, fo=64, mean (==identity for nh=1), no act ----
    {
        gemm_kernel<128, 64, 8, 8, 4><<<dim3(64 / 64, NNODES / 128), 256>>>(x2, W2, proj, NNODES, 1024, 64);
        gemm_kernel<128, 64, 8, 8, 4><<<dim3(64 / 64, NNODES / 128), 256>>>(x2, skip2, skip, NNODES, 1024, 64);
        int nh = 1, fo = 64;
        int nwarp = NNODES * nh;
        scores_kernel<<<(nwarp * 32 + 255) / 256, 256>>>(proj, a_src2, a_tgt2, ssrc, stgt, nh, fo);
        agg_kernel<<<dim3(NNODES, nh), fo>>>(proj, ssrc, stgt, skip, b2, x3, nh, fo, 0);
    }

    // ---- MLP head ----
    mlp_kernel<<<NCAND, 256>>>(x3, cand, mW1, mb1, mW2, mb2, mW3, mb3, (float*)d_out, out_size);
}

// round 2
// speedup vs baseline: 1.5565x; 1.5565x over previous
#include <cuda_runtime.h>
#include <math.h>
#include <stdint.h>

#define NNODES 16384
#define NEDGES 98304
#define NCAND  1024

// ---------------- scratch (static device globals; no allocation) ----------------
__device__ float g_x1[NNODES * 512];     // layer0 output
__device__ float g_x2[NNODES * 1024];    // layer1 output
__device__ float g_x3[NNODES * 64];      // layer2 output
__device__ float g_proj[NNODES * 1024];  // per-layer projection (max nh*fo = 1024)
__device__ float g_skip[NNODES * 1024];  // per-layer skip projection
__device__ float g_ssrc[NNODES * 8];
__device__ float g_stgt[NNODES * 8];
__device__ int   g_cnt[NNODES];
__device__ int   g_off[NNODES + 1];
__device__ int   g_cur[NNODES];
__device__ int   g_srcs[NEDGES];         // src node of each edge, sorted by tgt

// ---------------- CSR build ----------------
__global__ void zero_cnt_kernel() {
    int i = blockIdx.x * blockDim.x + threadIdx.x;
    if (i < NNODES) g_cnt[i] = 0;
}

__global__ void count_kernel(const int* __restrict__ tgt) {
    int e = blockIdx.x * blockDim.x + threadIdx.x;
    if (e < NEDGES) atomicAdd(&g_cnt[tgt[e]], 1);
}

__global__ void scan_kernel() {
    __shared__ int part[1024];
    const int PER = NNODES / 1024;  // 16
    int tid = threadIdx.x;
    int base = tid * PER;
    int local[PER];
    int s = 0;
#pragma unroll
    for (int i = 0; i < PER; i++) { local[i] = g_cnt[base + i]; s += local[i]; }
    part[tid] = s;
    __syncthreads();
    for (int d = 1; d < 1024; d <<= 1) {
        int v = (tid >= d) ? part[tid - d] : 0;
        __syncthreads();
        part[tid] += v;
        __syncthreads();
    }
    int run = (tid == 0) ? 0 : part[tid - 1];
#pragma unroll
    for (int i = 0; i < PER; i++) {
        g_off[base + i] = run;
        g_cur[base + i] = run;
        run += local[i];
    }
    if (tid == 1023) g_off[NNODES] = run;
}

__global__ void scatter_kernel(const int* __restrict__ src, const int* __restrict__ tgt) {
    int e = blockIdx.x * blockDim.x + threadIdx.x;
    if (e < NEDGES) {
        int p = atomicAdd(&g_cur[tgt[e]], 1);
        g_srcs[p] = src[e];
    }
}

// ---------------- layer 0 projection (K = 3) ----------------
__global__ void layer0_proj_kernel(const float* __restrict__ fea,
                                   const float* __restrict__ W,
                                   const float* __restrict__ S,
                                   float* __restrict__ proj,
                                   float* __restrict__ skip) {
    int n = blockIdx.x;
    float f0 = fea[n * 3 + 0], f1 = fea[n * 3 + 1], f2 = fea[n * 3 + 2];
    for (int m = threadIdx.x; m < 512; m += blockDim.x) {
        proj[n * 512 + m] = f0 * W[m] + f1 * W[512 + m] + f2 * W[1024 + m];
        skip[n * 512 + m] = f0 * S[m] + f1 * S[512 + m] + f2 * S[1024 + m];
    }
}

// ---------------- TF32 tensor-core GEMM: C[N,M] = A[N,K] @ B[K,M] ----------------
__device__ __forceinline__ uint32_t f2tf(float x) {
    uint32_t r;
    asm("cvt.rna.tf32.f32 %0, %1;" : "=r"(r) : "f"(x));
    return r;
}

// BM x BN block tile, BK=32 k-tile, WM x WN warp tile; mma m16n8k8 tf32.
// Requires N%BM==0, M%BN==0, K%32==0.
template <int BM, int BN, int WM, int WN>
__global__ void gemm_tf32_kernel(const float* __restrict__ A, const float* __restrict__ B,
                                 float* __restrict__ C, int N, int K, int M) {
    constexpr int BK = 32;
    constexpr int SA = BK + 4;   // stride ≡ 4 (mod 32): conflict-free A frag loads
    constexpr int SB = BN + 8;   // stride ≡ 8 (mod 32): conflict-free B frag loads
    constexpr int WARPS_M = BM / WM;
    constexpr int WARPS_N = BN / WN;
    constexpr int NT_ = (WARPS_M * WARPS_N) * 32;   // threads
    constexpr int MT = WM / 16;
    constexpr int NTILES = WN / 8;

    __shared__ uint32_t As[BM * SA];
    __shared__ uint32_t Bs[BK * SB];

    const int tid = threadIdx.x;
    const int warp = tid >> 5, lane = tid & 31;
    const int g = lane >> 2, tig = lane & 3;
    const int wy = warp / WARPS_N, wx = warp % WARPS_N;
    const int row0 = blockIdx.y * BM;
    const int col0 = blockIdx.x * BN;

    float c[MT][NTILES][4];
#pragma unroll
    for (int i = 0; i < MT; i++)
#pragma unroll
        for (int j = 0; j < NTILES; j++)
#pragma unroll
            for (int q = 0; q < 4; q++) c[i][j][q] = 0.f;

    for (int k0 = 0; k0 < K; k0 += BK) {
        // load A tile (BM x BK) as float4, convert to tf32
#pragma unroll
        for (int i = tid; i < BM * BK / 4; i += NT_) {
            int r = i / (BK / 4);
            int c4 = (i % (BK / 4)) * 4;
            float4 v = *reinterpret_cast<const float4*>(&A[(size_t)(row0 + r) * K + k0 + c4]);
            As[r * SA + c4 + 0] = f2tf(v.x);
            As[r * SA + c4 + 1] = f2tf(v.y);
            As[r * SA + c4 + 2] = f2tf(v.z);
            As[r * SA + c4 + 3] = f2tf(v.w);
        }
        // load B tile (BK x BN)
#pragma unroll
        for (int i = tid; i < BK * BN / 4; i += NT_) {
            int r = i / (BN / 4);
            int c4 = (i % (BN / 4)) * 4;
            float4 v = *reinterpret_cast<const float4*>(&B[(size_t)(k0 + r) * M + col0 + c4]);
            Bs[r * SB + c4 + 0] = f2tf(v.x);
            Bs[r * SB + c4 + 1] = f2tf(v.y);
            Bs[r * SB + c4 + 2] = f2tf(v.z);
            Bs[r * SB + c4 + 3] = f2tf(v.w);
        }
        __syncthreads();

#pragma unroll
        for (int kk = 0; kk < BK; kk += 8) {
            uint32_t a[MT][4], b[NTILES][2];
#pragma unroll
            for (int mt = 0; mt < MT; mt++) {
                int br = wy * WM + mt * 16;
                a[mt][0] = As[(br + g) * SA + kk + tig];
                a[mt][1] = As[(br + g + 8) * SA + kk + tig];
                a[mt][2] = As[(br + g) * SA + kk + tig + 4];
                a[mt][3] = As[(br + g + 8) * SA + kk + tig + 4];
            }
#pragma unroll
            for (int nt = 0; nt < NTILES; nt++) {
                int bc = wx * WN + nt * 8;
                b[nt][0] = Bs[(kk + tig) * SB + bc + g];
                b[nt][1] = Bs[(kk + tig + 4) * SB + bc + g];
            }
#pragma unroll
            for (int mt = 0; mt < MT; mt++)
#pragma unroll
                for (int nt = 0; nt < NTILES; nt++) {
                    asm volatile(
                        "mma.sync.aligned.m16n8k8.row.col.f32.tf32.tf32.f32 "
                        "{%0,%1,%2,%3}, {%4,%5,%6,%7}, {%8,%9}, {%0,%1,%2,%3};\n"
                        : "+f"(c[mt][nt][0]), "+f"(c[mt][nt][1]),
                          "+f"(c[mt][nt][2]), "+f"(c[mt][nt][3])
                        : "r"(a[mt][0]), "r"(a[mt][1]), "r"(a[mt][2]), "r"(a[mt][3]),
                          "r"(b[nt][0]), "r"(b[nt][1]));
                }
        }
        __syncthreads();
    }

    // store C
#pragma unroll
    for (int mt = 0; mt < MT; mt++) {
#pragma unroll
        for (int nt = 0; nt < NTILES; nt++) {
            int r = row0 + wy * WM + mt * 16 + g;
            int cc = col0 + wx * WN + nt * 8 + tig * 2;
            float2 v0 = make_float2(c[mt][nt][0], c[mt][nt][1]);
            float2 v1 = make_float2(c[mt][nt][2], c[mt][nt][3]);
            *reinterpret_cast<float2*>(&C[(size_t)r * M + cc]) = v0;
            *reinterpret_cast<float2*>(&C[(size_t)(r + 8) * M + cc]) = v1;
        }
    }
}

// ---------------- attention scores: s_src/s_tgt [N, nh] ----------------
__global__ void scores_kernel(const float* __restrict__ proj,
                              const float* __restrict__ a_src,
                              const float* __restrict__ a_tgt,
                              float* __restrict__ ssrc, float* __restrict__ stgt,
                              int nh, int fo) {
    int gw = (blockIdx.x * blockDim.x + threadIdx.x) >> 5;
    int lane = threadIdx.x & 31;
    int total = NNODES * nh;
    if (gw >= total) return;
    int n = gw / nh, h = gw % nh;
    const float* p = proj + (size_t)n * nh * fo + h * fo;
    float as_ = 0.f, at_ = 0.f;
    for (int f = lane; f < fo; f += 32) {
        float v = p[f];
        as_ += v * a_src[h * fo + f];
        at_ += v * a_tgt[h * fo + f];
    }
#pragma unroll
    for (int o = 16; o; o >>= 1) {
        as_ += __shfl_down_sync(0xffffffffu, as_, o);
        at_ += __shfl_down_sync(0xffffffffu, at_, o);
    }
    if (lane == 0) { ssrc[n * nh + h] = as_; stgt[n * nh + h] = at_; }
}

// ---------------- softmax-aggregate + skip + bias + activation ----------------
__global__ void agg_kernel(const float* __restrict__ proj,
                           const float* __restrict__ ssrc,
                           const float* __restrict__ stgt,
                           const float* __restrict__ skip,
                           const float* __restrict__ bias,
                           float* __restrict__ out,
                           int nh, int fo, int act) {
    int n = blockIdx.x, h = blockIdx.y;
    int tid = threadIdx.x;
    int beg = g_off[n], end = g_off[n + 1];
    float st = stgt[n * nh + h];
    __shared__ float red[128];

    float m = -1e30f;
    for (int j = beg + tid; j < end; j += blockDim.x) {
        float e = ssrc[g_srcs[j] * nh + h] + st;
        e = (e < 0.f) ? 0.2f * e : e;
        m = fmaxf(m, e);
    }
    red[tid] = m;
    __syncthreads();
    for (int s = blockDim.x >> 1; s; s >>= 1) {
        if (tid < s) red[tid] = fmaxf(red[tid], red[tid + s]);
        __syncthreads();
    }
    m = red[0];
    __syncthreads();

    float ssum = 0.f;
    for (int j = beg + tid; j < end; j += blockDim.x) {
        float e = ssrc[g_srcs[j] * nh + h] + st;
        e = (e < 0.f) ? 0.2f * e : e;
        ssum += expf(e - m);
    }
    red[tid] = ssum;
    __syncthreads();
    for (int s = blockDim.x >> 1; s; s >>= 1) {
        if (tid < s) red[tid] += red[tid + s];
        __syncthreads();
    }
    float inv = 1.f / (red[0] + 1e-16f);
    __syncthreads();

    float acc = 0.f;
    for (int j = beg; j < end; j++) {
        int s_ = g_srcs[j];
        float e = ssrc[s_ * nh + h] + st;
        e = (e < 0.f) ? 0.2f * e : e;
        float alpha = expf(e - m) * inv;
        acc += alpha * proj[(size_t)s_ * nh * fo + h * fo + tid];
    }
    size_t idx = (size_t)n * nh * fo + h * fo + tid;
    float v = acc + skip[idx] + bias[h * fo + tid];
    if (act) v = (v > 0.f) ? v : expm1f(v);
    out[idx] = v;
}

// ---------------- MLP head ----------------
__global__ void mlp_kernel(const float* __restrict__ x3, const int* __restrict__ cand,
                           const float* __restrict__ mW1, const float* __restrict__ mb1,
                           const float* __restrict__ mW2, const float* __restrict__ mb2,
                           const float* __restrict__ mW3, const float* __restrict__ mb3,
                           float* __restrict__ out, int out_size) {
    int c = blockIdx.x;
    int tid = threadIdx.x;  // 256 threads
    __shared__ float sc[64];
    __shared__ float sh[256];
    int cid = cand[c];
    if (tid < 64) sc[tid] = x3[cid * 64 + tid];
    __syncthreads();

    float acc = mb1[tid];
#pragma unroll 8
    for (int k = 0; k < 64; k++) acc += sc[k] * mW1[k * 256 + tid];
    float h1 = tanhf(acc);
    sh[tid] = h1;
    __syncthreads();

    acc = mb2[tid];
#pragma unroll 8
    for (int k = 0; k < 256; k++) acc += sh[k] * mW2[k * 256 + tid];
    float h2 = tanhf(acc);
    __syncthreads();

    sh[tid] = h2 * mW3[tid];
    __syncthreads();
    for (int s = 128; s; s >>= 1) {
        if (tid < s) sh[tid] += sh[tid + s];
        __syncthreads();
    }
    if (tid == 0) out[c] = sh[0] + mb3[0];
    if (out_size > NCAND && tid == 1 && (NCAND + c) < out_size) {
        out[NCAND + c] = (float)cid;
    }
}

// ---------------- launch ----------------
extern "C" void kernel_launch(void* const* d_in, const int* in_sizes, int n_in,
                              void* d_out, int out_size) {
    const float* fea  = (const float*)d_in[0];
    const int*   ei   = (const int*)d_in[1];
    const int*   cand = (const int*)d_in[2];
    const float* W0 = (const float*)d_in[3];
    const float* a_src0 = (const float*)d_in[4];
    const float* a_tgt0 = (const float*)d_in[5];
    const float* b0 = (const float*)d_in[6];
    const float* skip0 = (const float*)d_in[7];
    const float* W1 = (const float*)d_in[8];
    const float* a_src1 = (const float*)d_in[9];
    const float* a_tgt1 = (const float*)d_in[10];
    const float* b1 = (const float*)d_in[11];
    const float* skip1 = (const float*)d_in[12];
    const float* W2 = (const float*)d_in[13];
    const float* a_src2 = (const float*)d_in[14];
    const float* a_tgt2 = (const float*)d_in[15];
    const float* b2 = (const float*)d_in[16];
    const float* skip2 = (const float*)d_in[17];
    const float* mW1 = (const float*)d_in[18];
    const float* mb1 = (const float*)d_in[19];
    const float* mW2 = (const float*)d_in[20];
    const float* mb2 = (const float*)d_in[21];
    const float* mW3 = (const float*)d_in[22];
    const float* mb3 = (const float*)d_in[23];

    const int E = in_sizes[1] / 2;
    const int* src = ei;
    const int* tgt = ei + E;

    float *x1, *x2, *x3, *proj, *skip, *ssrc, *stgt;
    cudaGetSymbolAddress((void**)&x1,   g_x1);
    cudaGetSymbolAddress((void**)&x2,   g_x2);
    cudaGetSymbolAddress((void**)&x3,   g_x3);
    cudaGetSymbolAddress((void**)&proj, g_proj);
    cudaGetSymbolAddress((void**)&skip, g_skip);
    cudaGetSymbolAddress((void**)&ssrc, g_ssrc);
    cudaGetSymbolAddress((void**)&stgt, g_stgt);

    // ---- CSR build (by target) ----
    zero_cnt_kernel<<<(NNODES + 255) / 256, 256>>>();
    count_kernel<<<(NEDGES + 255) / 256, 256>>>(tgt);
    scan_kernel<<<1, 1024>>>();
    scatter_kernel<<<(NEDGES + 255) / 256, 256>>>(src, tgt);

    // ---- layer 0: nh=8, fo=64, concat, elu ----
    layer0_proj_kernel<<<NNODES, 128>>>(fea, W0, skip0, proj, skip);
    {
        int nh = 8, fo = 64;
        int nwarp = NNODES * nh;
        scores_kernel<<<(nwarp * 32 + 255) / 256, 256>>>(proj, a_src0, a_tgt0, ssrc, stgt, nh, fo);
        agg_kernel<<<dim3(NNODES, nh), fo>>>(proj, ssrc, stgt, skip, b0, x1, nh, fo, 1);
    }

    // ---- layer 1: nh=8, fo=128, concat, elu ----
    {
        // C[16384,1024] = x1[16384,512] @ W1/skip1  via TF32 tensor cores
        gemm_tf32_kernel<128, 128, 64, 32>
            <<<dim3(1024 / 128, NNODES / 128), 256>>>(x1, W1, proj, NNODES, 512, 1024);
        gemm_tf32_kernel<128, 128, 64, 32>
            <<<dim3(1024 / 128, NNODES / 128), 256>>>(x1, skip1, skip, NNODES, 512, 1024);
        int nh = 8, fo = 128;
        int nwarp = NNODES * nh;
        scores_kernel<<<(nwarp * 32 + 255) / 256, 256>>>(proj, a_src1, a_tgt1, ssrc, stgt, nh, fo);
        agg_kernel<<<dim3(NNODES, nh), fo>>>(proj, ssrc, stgt, skip, b1, x2, nh, fo, 1);
    }

    // ---- layer 2: nh=1, fo=64, no act ----
    {
        gemm_tf32_kernel<64, 64, 32, 32>
            <<<dim3(64 / 64, NNODES / 64), 128>>>(x2, W2, proj, NNODES, 1024, 64);
        gemm_tf32_kernel<64, 64, 32, 32>
            <<<dim3(64 / 64, NNODES / 64), 128>>>(x2, skip2, skip, NNODES, 1024, 64);
        int nh = 1, fo = 64;
        int nwarp = NNODES * nh;
        scores_kernel<<<(nwarp * 32 + 255) / 256, 256>>>(proj, a_src2, a_tgt2, ssrc, stgt, nh, fo);
        agg_kernel<<<dim3(NNODES, nh), fo>>>(proj, ssrc, stgt, skip, b2, x3, nh, fo, 0);
    }

    // ---- MLP head ----
    mlp_kernel<<<NCAND, 256>>>(x3, cand, mW1, mb1, mW2, mb2, mW3, mb3, (float*)d_out, out_size);
}

// round 3
// speedup vs baseline: 2.1793x; 1.4001x over previous
#include <cuda_runtime.h>
#include <math.h>
#include <stdint.h>

#define NNODES 16384
#define NEDGES 98304
#define NCAND  1024

// ---------------- scratch ----------------
__device__ float g_x1[NNODES * 512];     // layer0 output (stored as tf32 bits)
__device__ float g_x2[NNODES * 1024];    // layer1 output (stored as tf32 bits)
__device__ float g_x3[NNODES * 64];      // layer2 output (fp32)
__device__ float g_proj[NNODES * 1024];
__device__ float g_skip[NNODES * 1024];
__device__ float g_ssrc[NNODES * 8];
__device__ float g_stgt[NNODES * 8];
__device__ int   g_cnt[NNODES];
__device__ int   g_off[NNODES + 1];
__device__ int   g_cur[NNODES];
__device__ int   g_srcs[NEDGES];
// tf32-converted weights: W1(524288) skip1(524288) W2(65536) skip2(65536)
__device__ uint32_t g_wtf[1179648];

__device__ __forceinline__ uint32_t f2tf(float x) {
    uint32_t r;
    asm("cvt.rna.tf32.f32 %0, %1;" : "=r"(r) : "f"(x));
    return r;
}

// ---------------- CSR build ----------------
__global__ void zero_cnt_kernel() {
    int i = blockIdx.x * blockDim.x + threadIdx.x;
    if (i < NNODES) g_cnt[i] = 0;
}
__global__ void count_kernel(const int* __restrict__ tgt) {
    int e = blockIdx.x * blockDim.x + threadIdx.x;
    if (e < NEDGES) atomicAdd(&g_cnt[tgt[e]], 1);
}
__global__ void scan_kernel() {
    __shared__ int part[1024];
    const int PER = NNODES / 1024;
    int tid = threadIdx.x;
    int base = tid * PER;
    int local[PER];
    int s = 0;
#pragma unroll
    for (int i = 0; i < PER; i++) { local[i] = g_cnt[base + i]; s += local[i]; }
    part[tid] = s;
    __syncthreads();
    for (int d = 1; d < 1024; d <<= 1) {
        int v = (tid >= d) ? part[tid - d] : 0;
        __syncthreads();
        part[tid] += v;
        __syncthreads();
    }
    int run = (tid == 0) ? 0 : part[tid - 1];
#pragma unroll
    for (int i = 0; i < PER; i++) {
        g_off[base + i] = run;
        g_cur[base + i] = run;
        run += local[i];
    }
    if (tid == 1023) g_off[NNODES] = run;
}
__global__ void scatter_kernel(const int* __restrict__ src, const int* __restrict__ tgt) {
    int e = blockIdx.x * blockDim.x + threadIdx.x;
    if (e < NEDGES) {
        int p = atomicAdd(&g_cur[tgt[e]], 1);
        g_srcs[p] = src[e];
    }
}

// ---------------- weight tf32 conversion ----------------
__global__ void conv_tf32_kernel(const float* __restrict__ in, uint32_t* __restrict__ out, int n) {
    int i = blockIdx.x * blockDim.x + threadIdx.x;
    if (i < n) out[i] = f2tf(in[i]);
}

// ---------------- layer 0 projection (K = 3) ----------------
__global__ void layer0_proj_kernel(const float* __restrict__ fea,
                                   const float* __restrict__ W,
                                   const float* __restrict__ S,
                                   float* __restrict__ proj,
                                   float* __restrict__ skip) {
    int n = blockIdx.x;
    float f0 = fea[n * 3 + 0], f1 = fea[n * 3 + 1], f2 = fea[n * 3 + 2];
    for (int m = threadIdx.x; m < 512; m += blockDim.x) {
        proj[n * 512 + m] = f0 * W[m] + f1 * W[512 + m] + f2 * W[1024 + m];
        skip[n * 512 + m] = f0 * S[m] + f1 * S[512 + m] + f2 * S[1024 + m];
    }
}

// ---------------- cp.async helpers ----------------
__device__ __forceinline__ void cp16(void* s, const void* g) {
    uint32_t sa = (uint32_t)__cvta_generic_to_shared(s);
    asm volatile("cp.async.cg.shared.global [%0], [%1], 16;\n" :: "r"(sa), "l"(g));
}
__device__ __forceinline__ void cp_commit() { asm volatile("cp.async.commit_group;\n"); }
__device__ __forceinline__ void cp_wait1()  { asm volatile("cp.async.wait_group 1;\n"); }

// ---------------- dual-B TF32 tensor GEMM ----------------
// C0[N,M] = A@B0, C1[N,M] = A@B1.  A,B already tf32 bits.
// BM=128, BK=32. Warps 0-3 -> C0 (2x2, 64 x BN/2 each), warps 4-7 -> C1.
template <int BN>
__global__ __launch_bounds__(256, 1)
void gemm_dual_kernel(const uint32_t* __restrict__ A,
                      const uint32_t* __restrict__ B0, const uint32_t* __restrict__ B1,
                      float* __restrict__ C0, float* __restrict__ C1,
                      int N, int K, int M) {
    constexpr int BM = 128, BK = 32;
    constexpr int SA = BK + 4;     // bank = 4g+tig : conflict-free
    constexpr int SB = BN + 8;     // bank = 8tig+g : conflict-free
    constexpr int WN = BN / 2;
    constexpr int NT = WN / 8;     // 8-col mma tiles per warp
    constexpr int AW = BM * SA;    // words per A stage
    constexpr int BW = BK * SB;    // words per B matrix per stage

    extern __shared__ uint32_t sm[];
    uint32_t* As = sm;             // 2 stages
    uint32_t* Bs = sm + 2 * AW;    // 2 stages x 2 matrices

    const int tid = threadIdx.x;
    const int warp = tid >> 5, lane = tid & 31;
    const int g = lane >> 2, tig = lane & 3;
    const int half = warp >> 2;            // 0 -> (B0,C0), 1 -> (B1,C1)
    const int wsub = warp & 3;
    const int wy = wsub >> 1, wx = wsub & 1;
    const int row0 = blockIdx.y * BM;
    const int col0 = blockIdx.x * BN;
    const uint32_t* Bm = half ? B1 : B0;
    float* Cm = half ? C1 : C0;

    float acc[4][NT][4];
#pragma unroll
    for (int i = 0; i < 4; i++)
#pragma unroll
        for (int j = 0; j < NT; j++)
#pragma unroll
            for (int q = 0; q < 4; q++) acc[i][j][q] = 0.f;

    const int KT = K / BK;

    auto load_stage = [&](int s, int kt) {
        const int k0 = kt * BK;
        uint32_t* as = As + s * AW;
#pragma unroll
        for (int it = 0; it < 4; it++) {
            int idx = tid + it * 256;           // 1024 quads in A tile
            int r = idx >> 3, q = idx & 7;
            cp16(&as[r * SA + q * 4], &A[(size_t)(row0 + r) * K + k0 + q * 4]);
        }
        uint32_t* bs0 = Bs + (s * 2 + 0) * BW;
        uint32_t* bs1 = Bs + (s * 2 + 1) * BW;
        constexpr int QB = BK * BN / 4;         // quads per B matrix
#pragma unroll
        for (int it = 0; it < QB / 256; it++) {
            int idx = tid + it * 256;
            int r = idx / (BN / 4), q = idx % (BN / 4);
            size_t go = (size_t)(k0 + r) * M + col0 + q * 4;
            cp16(&bs0[r * SB + q * 4], &B0[go]);
            cp16(&bs1[r * SB + q * 4], &B1[go]);
        }
    };

    load_stage(0, 0);
    cp_commit();

    for (int kt = 0; kt < KT; kt++) {
        if (kt + 1 < KT) load_stage((kt + 1) & 1, kt + 1);
        cp_commit();
        cp_wait1();
        __syncthreads();

        const uint32_t* as = As + (kt & 1) * AW;
        const uint32_t* bs = Bs + ((kt & 1) * 2 + half) * BW;
#pragma unroll
        for (int kk = 0; kk < BK; kk += 8) {
            uint32_t a[4][4], b[NT][2];
#pragma unroll
            for (int mt = 0; mt < 4; mt++) {
                int br = wy * 64 + mt * 16;
                a[mt][0] = as[(br + g) * SA + kk + tig];
                a[mt][1] = as[(br + g + 8) * SA + kk + tig];
                a[mt][2] = as[(br + g) * SA + kk + tig + 4];
                a[mt][3] = as[(br + g + 8) * SA + kk + tig + 4];
            }
#pragma unroll
            for (int nt = 0; nt < NT; nt++) {
                int bc = wx * WN + nt * 8;
                b[nt][0] = bs[(kk + tig) * SB + bc + g];
                b[nt][1] = bs[(kk + tig + 4) * SB + bc + g];
            }
#pragma unroll
            for (int mt = 0; mt < 4; mt++)
#pragma unroll
                for (int nt = 0; nt < NT; nt++) {
                    asm volatile(
                        "mma.sync.aligned.m16n8k8.row.col.f32.tf32.tf32.f32 "
                        "{%0,%1,%2,%3}, {%4,%5,%6,%7}, {%8,%9}, {%0,%1,%2,%3};\n"
                        : "+f"(acc[mt][nt][0]), "+f"(acc[mt][nt][1]),
                          "+f"(acc[mt][nt][2]), "+f"(acc[mt][nt][3])
                        : "r"(a[mt][0]), "r"(a[mt][1]), "r"(a[mt][2]), "r"(a[mt][3]),
                          "r"(b[nt][0]), "r"(b[nt][1]));
                }
        }
        __syncthreads();
    }

#pragma unroll
    for (int mt = 0; mt < 4; mt++) {
#pragma unroll
        for (int nt = 0; nt < NT; nt++) {
            int r = row0 + wy * 64 + mt * 16 + g;
            int cc = col0 + wx * WN + nt * 8 + tig * 2;
            *reinterpret_cast<float2*>(&Cm[(size_t)r * M + cc]) =
                make_float2(acc[mt][nt][0], acc[mt][nt][1]);
            *reinterpret_cast<float2*>(&Cm[(size_t)(r + 8) * M + cc]) =
                make_float2(acc[mt][nt][2], acc[mt][nt][3]);
        }
    }
}

// ---------------- attention scores ----------------
__global__ void scores_kernel(const float* __restrict__ proj,
                              const float* __restrict__ a_src,
                              const float* __restrict__ a_tgt,
                              float* __restrict__ ssrc, float* __restrict__ stgt,
                              int nh, int fo) {
    int gw = (blockIdx.x * blockDim.x + threadIdx.x) >> 5;
    int lane = threadIdx.x & 31;
    int total = NNODES * nh;
    if (gw >= total) return;
    int n = gw / nh, h = gw % nh;
    const float* p = proj + (size_t)n * nh * fo + h * fo;
    float as_ = 0.f, at_ = 0.f;
    for (int f = lane; f < fo; f += 32) {
        float v = p[f];
        as_ += v * a_src[h * fo + f];
        at_ += v * a_tgt[h * fo + f];
    }
#pragma unroll
    for (int o = 16; o; o >>= 1) {
        as_ += __shfl_down_sync(0xffffffffu, as_, o);
        at_ += __shfl_down_sync(0xffffffffu, at_, o);
    }
    if (lane == 0) { ssrc[n * nh + h] = as_; stgt[n * nh + h] = at_; }
}

// ---------------- softmax-aggregate + skip + bias + activation ----------------
// otf: write output as tf32 bits (consumed only by GEMM)
__global__ void agg_kernel(const float* __restrict__ proj,
                           const float* __restrict__ ssrc,
                           const float* __restrict__ stgt,
                           const float* __restrict__ skip,
                           const float* __restrict__ bias,
                           float* __restrict__ out,
                           int nh, int fo, int act, int otf) {
    int n = blockIdx.x, h = blockIdx.y;
    int tid = threadIdx.x;
    int beg = g_off[n], end = g_off[n + 1];
    float st = stgt[n * nh + h];
    __shared__ float red[128];

    float m = -1e30f;
    for (int j = beg + tid; j < end; j += blockDim.x) {
        float e = ssrc[g_srcs[j] * nh + h] + st;
        e = (e < 0.f) ? 0.2f * e : e;
        m = fmaxf(m, e);
    }
    red[tid] = m;
    __syncthreads();
    for (int s = blockDim.x >> 1; s; s >>= 1) {
        if (tid < s) red[tid] = fmaxf(red[tid], red[tid + s]);
        __syncthreads();
    }
    m = red[0];
    __syncthreads();

    float ssum = 0.f;
    for (int j = beg + tid; j < end; j += blockDim.x) {
        float e = ssrc[g_srcs[j] * nh + h] + st;
        e = (e < 0.f) ? 0.2f * e : e;
        ssum += expf(e - m);
    }
    red[tid] = ssum;
    __syncthreads();
    for (int s = blockDim.x >> 1; s; s >>= 1) {
        if (tid < s) red[tid] += red[tid + s];
        __syncthreads();
    }
    float inv = 1.f / (red[0] + 1e-16f);
    __syncthreads();

    float acc = 0.f;
    for (int j = beg; j < end; j++) {
        int s_ = g_srcs[j];
        float e = ssrc[s_ * nh + h] + st;
        e = (e < 0.f) ? 0.2f * e : e;
        float alpha = expf(e - m) * inv;
        acc += alpha * proj[(size_t)s_ * nh * fo + h * fo + tid];
    }
    size_t idx = (size_t)n * nh * fo + h * fo + tid;
    float v = acc + skip[idx] + bias[h * fo + tid];
    if (act) v = (v > 0.f) ? v : expm1f(v);
    out[idx] = otf ? __uint_as_float(f2tf(v)) : v;
}

// ---------------- MLP head ----------------
__global__ void mlp_kernel(const float* __restrict__ x3, const int* __restrict__ cand,
                           const float* __restrict__ mW1, const float* __restrict__ mb1,
                           const float* __restrict__ mW2, const float* __restrict__ mb2,
                           const float* __restrict__ mW3, const float* __restrict__ mb3,
                           float* __restrict__ out, int out_size) {
    int c = blockIdx.x;
    int tid = threadIdx.x;
    __shared__ float sc[64];
    __shared__ float sh[256];
    int cid = cand[c];
    if (tid < 64) sc[tid] = x3[cid * 64 + tid];
    __syncthreads();

    float acc = mb1[tid];
#pragma unroll 8
    for (int k = 0; k < 64; k++) acc += sc[k] * mW1[k * 256 + tid];
    float h1 = tanhf(acc);
    sh[tid] = h1;
    __syncthreads();

    acc = mb2[tid];
#pragma unroll 8
    for (int k = 0; k < 256; k++) acc += sh[k] * mW2[k * 256 + tid];
    float h2 = tanhf(acc);
    __syncthreads();

    sh[tid] = h2 * mW3[tid];
    __syncthreads();
    for (int s = 128; s; s >>= 1) {
        if (tid < s) sh[tid] += sh[tid + s];
        __syncthreads();
    }
    if (tid == 0) out[c] = sh[0] + mb3[0];
    if (out_size > NCAND && tid == 1 && (NCAND + c) < out_size) {
        out[NCAND + c] = (float)cid;
    }
}

// ---------------- launch ----------------
extern "C" void kernel_launch(void* const* d_in, const int* in_sizes, int n_in,
                              void* d_out, int out_size) {
    const float* fea  = (const float*)d_in[0];
    const int*   ei   = (const int*)d_in[1];
    const int*   cand = (const int*)d_in[2];
    const float* W0 = (const float*)d_in[3];
    const float* a_src0 = (const float*)d_in[4];
    const float* a_tgt0 = (const float*)d_in[5];
    const float* b0 = (const float*)d_in[6];
    const float* skip0 = (const float*)d_in[7];
    const float* W1 = (const float*)d_in[8];
    const float* a_src1 = (const float*)d_in[9];
    const float* a_tgt1 = (const float*)d_in[10];
    const float* b1 = (const float*)d_in[11];
    const float* skip1 = (const float*)d_in[12];
    const float* W2 = (const float*)d_in[13];
    const float* a_src2 = (const float*)d_in[14];
    const float* a_tgt2 = (const float*)d_in[15];
    const float* b2 = (const float*)d_in[16];
    const float* skip2 = (const float*)d_in[17];
    const float* mW1 = (const float*)d_in[18];
    const float* mb1 = (const float*)d_in[19];
    const float* mW2 = (const float*)d_in[20];
    const float* mb2 = (const float*)d_in[21];
    const float* mW3 = (const float*)d_in[22];
    const float* mb3 = (const float*)d_in[23];

    const int E = in_sizes[1] / 2;
    const int* src = ei;
    const int* tgt = ei + E;

    float *x1, *x2, *x3, *proj, *skip, *ssrc, *stgt;
    uint32_t* wtf;
    cudaGetSymbolAddress((void**)&x1,   g_x1);
    cudaGetSymbolAddress((void**)&x2,   g_x2);
    cudaGetSymbolAddress((void**)&x3,   g_x3);
    cudaGetSymbolAddress((void**)&proj, g_proj);
    cudaGetSymbolAddress((void**)&skip, g_skip);
    cudaGetSymbolAddress((void**)&ssrc, g_ssrc);
    cudaGetSymbolAddress((void**)&stgt, g_stgt);
    cudaGetSymbolAddress((void**)&wtf,  g_wtf);

    uint32_t* W1t = wtf;
    uint32_t* S1t = wtf + 524288;
    uint32_t* W2t = wtf + 1048576;
    uint32_t* S2t = wtf + 1114112;

    const int SMEM_L1 = (2 * 128 * 36 + 2 * 2 * 32 * 136) * 4;  // 106496
    const int SMEM_L2 = (2 * 128 * 36 + 2 * 2 * 32 * 72) * 4;   // 73728
    cudaFuncSetAttribute(gemm_dual_kernel<128>,
                         cudaFuncAttributeMaxDynamicSharedMemorySize, SMEM_L1);
    cudaFuncSetAttribute(gemm_dual_kernel<64>,
                         cudaFuncAttributeMaxDynamicSharedMemorySize, SMEM_L2);

    // ---- CSR build + weight conversion ----
    zero_cnt_kernel<<<(NNODES + 255) / 256, 256>>>();
    count_kernel<<<(NEDGES + 255) / 256, 256>>>(tgt);
    scan_kernel<<<1, 1024>>>();
    scatter_kernel<<<(NEDGES + 255) / 256, 256>>>(src, tgt);
    conv_tf32_kernel<<<2048, 256>>>(W1, W1t, 524288);
    conv_tf32_kernel<<<2048, 256>>>(skip1, S1t, 524288);
    conv_tf32_kernel<<<256, 256>>>(W2, W2t, 65536);
    conv_tf32_kernel<<<256, 256>>>(skip2, S2t, 65536);

    // ---- layer 0: nh=8, fo=64, concat, elu ----
    layer0_proj_kernel<<<NNODES, 128>>>(fea, W0, skip0, proj, skip);
    {
        int nh = 8, fo = 64;
        int nwarp = NNODES * nh;
        scores_kernel<<<(nwarp * 32 + 255) / 256, 256>>>(proj, a_src0, a_tgt0, ssrc, stgt, nh, fo);
        agg_kernel<<<dim3(NNODES, nh), fo>>>(proj, ssrc, stgt, skip, b0, x1, nh, fo, 1, 1);
    }

    // ---- layer 1: nh=8, fo=128, concat, elu ----
    {
        gemm_dual_kernel<128><<<dim3(1024 / 128, NNODES / 128), 256, SMEM_L1>>>(
            (const uint32_t*)x1, W1t, S1t, proj, skip, NNODES, 512, 1024);
        int nh = 8, fo = 128;
        int nwarp = NNODES * nh;
        scores_kernel<<<(nwarp * 32 + 255) / 256, 256>>>(proj, a_src1, a_tgt1, ssrc, stgt, nh, fo);
        agg_kernel<<<dim3(NNODES, nh), fo>>>(proj, ssrc, stgt, skip, b1, x2, nh, fo, 1, 1);
    }

    // ---- layer 2: nh=1, fo=64, no act ----
    {
        gemm_dual_kernel<64><<<dim3(1, NNODES / 128), 256, SMEM_L2>>>(
            (const uint32_t*)x2, W2t, S2t, proj, skip, NNODES, 1024, 64);
        int nh = 1, fo = 64;
        int nwarp = NNODES * nh;
        scores_kernel<<<(nwarp * 32 + 255) / 256, 256>>>(proj, a_src2, a_tgt2, ssrc, stgt, nh, fo);
        agg_kernel<<<dim3(NNODES, nh), fo>>>(proj, ssrc, stgt, skip, b2, x3, nh, fo, 0, 0);
    }

    // ---- MLP head ----
    mlp_kernel<<<NCAND, 256>>>(x3, cand, mW1, mb1, mW2, mb2, mW3, mb3, (float*)d_out, out_size);
}

// round 5
// speedup vs baseline: 2.4002x; 1.1014x over previous
#include <cuda_runtime.h>
#include <math.h>
#include <stdint.h>

#define NNODES 16384
#define NEDGES 98304
#define NCAND  1024

// ---------------- scratch ----------------
__device__ float g_x1[NNODES * 512];     // layer0 output (tf32 bits)
__device__ float g_x2[NNODES * 1024];    // layer1 output (tf32 bits)
__device__ float g_x3[NNODES * 64];      // layer2 output (fp32)
__device__ float g_proj[NNODES * 1024];
__device__ float g_skip[NNODES * 1024];
__device__ float g_ssrc[NNODES * 8];
__device__ float g_stgt[NNODES * 8];
__device__ int   g_cnt[NNODES];
__device__ int   g_off[NNODES + 1];
__device__ int   g_cur[NNODES];
__device__ int   g_srcs[NEDGES];
__device__ float g_csrc[24];             // layer0 folded a_src: [8 heads][3]
__device__ float g_ctgt[24];
// tf32 weights: W1(524288) skip1(524288) W2(65536) skip2(65536)
__device__ uint32_t g_wtf[1179648];

__device__ __forceinline__ uint32_t f2tf(float x) {
    uint32_t r;
    asm("cvt.rna.tf32.f32 %0, %1;" : "=r"(r) : "f"(x));
    return r;
}

// ---------------- CSR build ----------------
__global__ void zero_cnt_kernel() {
    int i = blockIdx.x * blockDim.x + threadIdx.x;
    if (i < NNODES) g_cnt[i] = 0;
}
__global__ void count_kernel(const int* __restrict__ tgt) {
    int e = blockIdx.x * blockDim.x + threadIdx.x;
    if (e < NEDGES) atomicAdd(&g_cnt[tgt[e]], 1);
}
__global__ void scan_kernel() {
    __shared__ int part[1024];
    const int PER = NNODES / 1024;
    int tid = threadIdx.x;
    int base = tid * PER;
    int local[PER];
    int s = 0;
#pragma unroll
    for (int i = 0; i < PER; i++) { local[i] = g_cnt[base + i]; s += local[i]; }
    part[tid] = s;
    __syncthreads();
    for (int d = 1; d < 1024; d <<= 1) {
        int v = (tid >= d) ? part[tid - d] : 0;
        __syncthreads();
        part[tid] += v;
        __syncthreads();
    }
    int run = (tid == 0) ? 0 : part[tid - 1];
#pragma unroll
    for (int i = 0; i < PER; i++) {
        g_off[base + i] = run;
        g_cur[base + i] = run;
        run += local[i];
    }
    if (tid == 1023) g_off[NNODES] = run;
}
__global__ void scatter_kernel(const int* __restrict__ src, const int* __restrict__ tgt) {
    int e = blockIdx.x * blockDim.x + threadIdx.x;
    if (e < NEDGES) {
        int p = atomicAdd(&g_cur[tgt[e]], 1);
        g_srcs[p] = src[e];
    }
}

// ---------------- weight tf32 conversion ----------------
__global__ void conv_tf32_kernel(const float* __restrict__ in, uint32_t* __restrict__ out, int n) {
    int i = blockIdx.x * blockDim.x + threadIdx.x;
    if (i < n) out[i] = f2tf(in[i]);
}

// ---------------- layer 0 folded score coefficients ----------------
// c_src[h][d] = sum_f W0[d][h*64+f] * a_src0[h][f]
__global__ void precomp_c_kernel(const float* __restrict__ W0,
                                 const float* __restrict__ a_src0,
                                 const float* __restrict__ a_tgt0) {
    int t = threadIdx.x;   // 48 threads
    int isT = t >= 24;
    int i = isT ? t - 24 : t;
    int h = i / 3, d = i % 3;
    const float* a = isT ? a_tgt0 : a_src0;
    float s = 0.f;
    for (int f = 0; f < 64; f++)
        s += W0[d * 512 + h * 64 + f] * a[h * 64 + f];
    (isT ? g_ctgt : g_csrc)[i] = s;
}

// ---------------- layer 0 node scores (tiny) ----------------
__global__ void l0_scores_kernel(const float* __restrict__ fea) {
    int i = blockIdx.x * blockDim.x + threadIdx.x;  // n*8+h
    if (i >= NNODES * 8) return;
    int n = i >> 3, h = i & 7;
    float f0 = fea[n * 3 + 0], f1 = fea[n * 3 + 1], f2 = fea[n * 3 + 2];
    g_ssrc[i] = f0 * g_csrc[h * 3] + f1 * g_csrc[h * 3 + 1] + f2 * g_csrc[h * 3 + 2];
    g_stgt[i] = f0 * g_ctgt[h * 3] + f1 * g_ctgt[h * 3 + 1] + f2 * g_ctgt[h * 3 + 2];
}

// ---------------- fused layer 0 agg: proj/skip computed on the fly ----------------
// block = 512 threads = one node; out elem tid: head = tid>>6
__global__ __launch_bounds__(512)
void agg0_kernel(const float* __restrict__ fea,
                 const float* __restrict__ W0, const float* __restrict__ S0,
                 const float* __restrict__ b0, float* __restrict__ out) {
    const int n = blockIdx.x;
    const int tid = threadIdx.x;
    const int warp = tid >> 5, lane = tid & 31;
    const int beg = g_off[n], end = g_off[n + 1];

    const float w0 = W0[tid], w1 = W0[512 + tid], w2 = W0[1024 + tid];
    const float s0 = S0[tid], s1 = S0[512 + tid], s2 = S0[1024 + tid];

    __shared__ float mh[8], ivh[8];
    __shared__ float al[32 * 8];
    __shared__ float sf[32 * 3];

    if (warp < 8) {
        const int h = warp;
        const float st = g_stgt[n * 8 + h];
        float m = -1e30f;
        for (int j = beg + lane; j < end; j += 32) {
            float e = g_ssrc[g_srcs[j] * 8 + h] + st;
            e = (e < 0.f) ? 0.2f * e : e;
            m = fmaxf(m, e);
        }
#pragma unroll
        for (int o = 16; o; o >>= 1) m = fmaxf(m, __shfl_xor_sync(0xffffffffu, m, o));
        float ss = 0.f;
        for (int j = beg + lane; j < end; j += 32) {
            float e = g_ssrc[g_srcs[j] * 8 + h] + st;
            e = (e < 0.f) ? 0.2f * e : e;
            ss += expf(e - m);
        }
#pragma unroll
        for (int o = 16; o; o >>= 1) ss += __shfl_xor_sync(0xffffffffu, ss, o);
        if (lane == 0) { mh[h] = m; ivh[h] = 1.f / (ss + 1e-16f); }
    }
    __syncthreads();

    const int myh = tid >> 6;
    float acc = 0.f;
    for (int j0 = beg; j0 < end; j0 += 32) {
        const int nj = min(32, end - j0);
        if (tid < 256) {
            const int l = tid & 31, h = tid >> 5;
            if (l < nj) {
                const int s = g_srcs[j0 + l];
                const float st = g_stgt[n * 8 + h];
                float e = g_ssrc[s * 8 + h] + st;
                e = (e < 0.f) ? 0.2f * e : e;
                al[l * 8 + h] = expf(e - mh[h]) * ivh[h];
                if (h == 0) {
                    sf[l * 3 + 0] = fea[s * 3 + 0];
                    sf[l * 3 + 1] = fea[s * 3 + 1];
                    sf[l * 3 + 2] = fea[s * 3 + 2];
                }
            }
        }
        __syncthreads();
        for (int l = 0; l < nj; l++) {
            const float a = al[l * 8 + myh];
            acc += a * (sf[l * 3] * w0 + sf[l * 3 + 1] * w1 + sf[l * 3 + 2] * w2);
        }
        __syncthreads();
    }

    const float f0 = fea[n * 3 + 0], f1 = fea[n * 3 + 1], f2 = fea[n * 3 + 2];
    float v = acc + (f0 * s0 + f1 * s1 + f2 * s2) + b0[tid];
    v = (v > 0.f) ? v : expm1f(v);
    out[n * 512 + tid] = __uint_as_float(f2tf(v));
}

// ---------------- cp.async helpers ----------------
__device__ __forceinline__ void cp16(void* s, const void* g) {
    uint32_t sa = (uint32_t)__cvta_generic_to_shared(s);
    asm volatile("cp.async.cg.shared.global [%0], [%1], 16;\n" :: "r"(sa), "l"(g));
}
__device__ __forceinline__ void cp_commit() { asm volatile("cp.async.commit_group;\n"); }

// ---------------- dual-B TF32 tensor GEMM, 3-stage pipeline ----------------
// C0[N,M] = A@B0, C1[N,M] = A@B1.  A,B already tf32 bits, B row-major [K,M].
template <int BN>
__global__ __launch_bounds__(256, 1)
void gemm_dual_kernel(const uint32_t* __restrict__ A,
                      const uint32_t* __restrict__ B0, const uint32_t* __restrict__ B1,
                      float* __restrict__ C0, float* __restrict__ C1,
                      int N, int K, int M) {
    constexpr int BM = 128, BK = 32;
    constexpr int SA = BK + 4;
    constexpr int SB = BN + 8;
    constexpr int WN = BN / 2;
    constexpr int NT = WN / 8;
    constexpr int AW = BM * SA;
    constexpr int BW = BK * SB;
    constexpr int STW = AW + 2 * BW;   // words per stage

    extern __shared__ uint32_t sm[];

    const int tid = threadIdx.x;
    const int warp = tid >> 5, lane = tid & 31;
    const int g = lane >> 2, tig = lane & 3;
    const int half = warp >> 2;
    const int wsub = warp & 3;
    const int wy = wsub >> 1, wx = wsub & 1;
    const int row0 = blockIdx.y * BM;
    const int col0 = blockIdx.x * BN;
    float* Cm = half ? C1 : C0;

    float acc[4][NT][4];
#pragma unroll
    for (int i = 0; i < 4; i++)
#pragma unroll
        for (int j = 0; j < NT; j++)
#pragma unroll
            for (int q = 0; q < 4; q++) acc[i][j][q] = 0.f;

    const int KT = K / BK;

    auto load_stage = [&](int s, int c) {
        const int k0 = c * BK;
        uint32_t* as = sm + s * STW;
#pragma unroll
        for (int it = 0; it < 4; it++) {
            int idx = tid + it * 256;
            int r = idx >> 3, q = idx & 7;
            cp16(&as[r * SA + q * 4], &A[(size_t)(row0 + r) * K + k0 + q * 4]);
        }
        uint32_t* bs0 = sm + s * STW + AW;
        uint32_t* bs1 = bs0 + BW;
        constexpr int QB = BK * BN / 4;
#pragma unroll
        for (int it = 0; it < QB / 256; it++) {
            int idx = tid + it * 256;
            int r = idx / (BN / 4), q = idx % (BN / 4);
            size_t go = (size_t)(k0 + r) * M + col0 + q * 4;
            cp16(&bs0[r * SB + q * 4], &B0[go]);
            cp16(&bs1[r * SB + q * 4], &B1[go]);
        }
        cp_commit();
    };

    load_stage(0, 0);
    load_stage(1, 1);

    for (int c = 0; c < KT; c++) {
        if (c + 2 < KT) {
            load_stage((c + 2) % 3, c + 2);
            asm volatile("cp.async.wait_group 2;\n");
        } else {
            asm volatile("cp.async.wait_group 0;\n");
        }
        __syncthreads();

        const uint32_t* as = sm + (c % 3) * STW;
        const uint32_t* bs = as + AW + half * BW;
#pragma unroll
        for (int kk = 0; kk < BK; kk += 8) {
            uint32_t a[4][4], b[NT][2];
#pragma unroll
            for (int mt = 0; mt < 4; mt++) {
                int br = wy * 64 + mt * 16;
                a[mt][0] = as[(br + g) * SA + kk + tig];
                a[mt][1] = as[(br + g + 8) * SA + kk + tig];
                a[mt][2] = as[(br + g) * SA + kk + tig + 4];
                a[mt][3] = as[(br + g + 8) * SA + kk + tig + 4];
            }
#pragma unroll
            for (int nt = 0; nt < NT; nt++) {
                int bc = wx * WN + nt * 8;
                b[nt][0] = bs[(kk + tig) * SB + bc + g];
                b[nt][1] = bs[(kk + tig + 4) * SB + bc + g];
            }
#pragma unroll
            for (int mt = 0; mt < 4; mt++)
#pragma unroll
                for (int nt = 0; nt < NT; nt++) {
                    asm volatile(
                        "mma.sync.aligned.m16n8k8.row.col.f32.tf32.tf32.f32 "
                        "{%0,%1,%2,%3}, {%4,%5,%6,%7}, {%8,%9}, {%0,%1,%2,%3};\n"
                        : "+f"(acc[mt][nt][0]), "+f"(acc[mt][nt][1]),
                          "+f"(acc[mt][nt][2]), "+f"(acc[mt][nt][3])
                        : "r"(a[mt][0]), "r"(a[mt][1]), "r"(a[mt][2]), "r"(a[mt][3]),
                          "r"(b[nt][0]), "r"(b[nt][1]));
                }
        }
        __syncthreads();
    }

#pragma unroll
    for (int mt = 0; mt < 4; mt++) {
#pragma unroll
        for (int nt = 0; nt < NT; nt++) {
            int r = row0 + wy * 64 + mt * 16 + g;
            int cc = col0 + wx * WN + nt * 8 + tig * 2;
            *reinterpret_cast<float2*>(&Cm[(size_t)r * M + cc]) =
                make_float2(acc[mt][nt][0], acc[mt][nt][1]);
            *reinterpret_cast<float2*>(&Cm[(size_t)(r + 8) * M + cc]) =
                make_float2(acc[mt][nt][2], acc[mt][nt][3]);
        }
    }
}

// ---------------- attention scores (layers 1,2) ----------------
__global__ void scores_kernel(const float* __restrict__ proj,
                              const float* __restrict__ a_src,
                              const float* __restrict__ a_tgt,
                              float* __restrict__ ssrc, float* __restrict__ stgt,
                              int nh, int fo) {
    int gw = (blockIdx.x * blockDim.x + threadIdx.x) >> 5;
    int lane = threadIdx.x & 31;
    int total = NNODES * nh;
    if (gw >= total) return;
    int n = gw / nh, h = gw % nh;
    const float* p = proj + (size_t)n * nh * fo + h * fo;
    float as_ = 0.f, at_ = 0.f;
    for (int f = lane; f < fo; f += 32) {
        float v = p[f];
        as_ += v * a_src[h * fo + f];
        at_ += v * a_tgt[h * fo + f];
    }
#pragma unroll
    for (int o = 16; o; o >>= 1) {
        as_ += __shfl_down_sync(0xffffffffu, as_, o);
        at_ += __shfl_down_sync(0xffffffffu, at_, o);
    }
    if (lane == 0) { ssrc[n * nh + h] = as_; stgt[n * nh + h] = at_; }
}

// ---------------- softmax-aggregate (layers 1,2) ----------------
__global__ void agg_kernel(const float* __restrict__ proj,
                           const float* __restrict__ ssrc,
                           const float* __restrict__ stgt,
                           const float* __restrict__ skip,
                           const float* __restrict__ bias,
                           float* __restrict__ out,
                           int nh, int fo, int act, int otf) {
    int n = blockIdx.x, h = blockIdx.y;
    int tid = threadIdx.x;
    int beg = g_off[n], end = g_off[n + 1];
    float st = stgt[n * nh + h];
    __shared__ float red[128];

    float m = -1e30f;
    for (int j = beg + tid; j < end; j += blockDim.x) {
        float e = ssrc[g_srcs[j] * nh + h] + st;
        e = (e < 0.f) ? 0.2f * e : e;
        m = fmaxf(m, e);
    }
    red[tid] = m;
    __syncthreads();
    for (int s = blockDim.x >> 1; s; s >>= 1) {
        if (tid < s) red[tid] = fmaxf(red[tid], red[tid + s]);
        __syncthreads();
    }
    m = red[0];
    __syncthreads();

    float ssum = 0.f;
    for (int j = beg + tid; j < end; j += blockDim.x) {
        float e = ssrc[g_srcs[j] * nh + h] + st;
        e = (e < 0.f) ? 0.2f * e : e;
        ssum += expf(e - m);
    }
    red[tid] = ssum;
    __syncthreads();
    for (int s = blockDim.x >> 1; s; s >>= 1) {
        if (tid < s) red[tid] += red[tid + s];
        __syncthreads();
    }
    float inv = 1.f / (red[0] + 1e-16f);
    __syncthreads();

    float acc = 0.f;
    for (int j = beg; j < end; j++) {
        int s_ = g_srcs[j];
        float e = ssrc[s_ * nh + h] + st;
        e = (e < 0.f) ? 0.2f * e : e;
        float alpha = expf(e - m) * inv;
        acc += alpha * proj[(size_t)s_ * nh * fo + h * fo + tid];
    }
    size_t idx = (size_t)n * nh * fo + h * fo + tid;
    float v = acc + skip[idx] + bias[h * fo + tid];
    if (act) v = (v > 0.f) ? v : expm1f(v);
    out[idx] = otf ? __uint_as_float(f2tf(v)) : v;
}

// ---------------- MLP head ----------------
__global__ void mlp_kernel(const float* __restrict__ x3, const int* __restrict__ cand,
                           const float* __restrict__ mW1, const float* __restrict__ mb1,
                           const float* __restrict__ mW2, const float* __restrict__ mb2,
                           const float* __restrict__ mW3, const float* __restrict__ mb3,
                           float* __restrict__ out, int out_size) {
    int c = blockIdx.x;
    int tid = threadIdx.x;
    __shared__ float sc[64];
    __shared__ float sh[256];
    int cid = cand[c];
    if (tid < 64) sc[tid] = x3[cid * 64 + tid];
    __syncthreads();

    float acc = mb1[tid];
#pragma unroll 8
    for (int k = 0; k < 64; k++) acc += sc[k] * mW1[k * 256 + tid];
    float h1 = tanhf(acc);
    sh[tid] = h1;
    __syncthreads();

    acc = mb2[tid];
#pragma unroll 8
    for (int k = 0; k < 256; k++) acc += sh[k] * mW2[k * 256 + tid];
    float h2 = tanhf(acc);
    __syncthreads();

    sh[tid] = h2 * mW3[tid];
    __syncthreads();
    for (int s = 128; s; s >>= 1) {
        if (tid < s) sh[tid] += sh[tid + s];
        __syncthreads();
    }
    if (tid == 0) out[c] = sh[0] + mb3[0];
    if (out_size > NCAND && tid == 1 && (NCAND + c) < out_size) {
        out[NCAND + c] = (float)cid;
    }
}

// ---------------- launch ----------------
extern "C" void kernel_launch(void* const* d_in, const int* in_sizes, int n_in,
                              void* d_out, int out_size) {
    const float* fea  = (const float*)d_in[0];
    const int*   ei   = (const int*)d_in[1];
    const int*   cand = (const int*)d_in[2];
    const float* W0 = (const float*)d_in[3];
    const float* a_src0 = (const float*)d_in[4];
    const float* a_tgt0 = (const float*)d_in[5];
    const float* b0 = (const float*)d_in[6];
    const float* skip0 = (const float*)d_in[7];
    const float* W1 = (const float*)d_in[8];
    const float* a_src1 = (const float*)d_in[9];
    const float* a_tgt1 = (const float*)d_in[10];
    const float* b1 = (const float*)d_in[11];
    const float* skip1 = (const float*)d_in[12];
    const float* W2 = (const float*)d_in[13];
    const float* a_src2 = (const float*)d_in[14];
    const float* a_tgt2 = (const float*)d_in[15];
    const float* b2 = (const float*)d_in[16];
    const float* skip2 = (const float*)d_in[17];
    const float* mW1 = (const float*)d_in[18];
    const float* mb1 = (const float*)d_in[19];
    const float* mW2 = (const float*)d_in[20];
    const float* mb2 = (const float*)d_in[21];
    const float* mW3 = (const float*)d_in[22];
    const float* mb3 = (const float*)d_in[23];

    const int E = in_sizes[1] / 2;
    const int* src = ei;
    const int* tgt = ei + E;

    float *x1, *x2, *x3, *proj, *skip, *ssrc, *stgt;
    uint32_t* wtf;
    cudaGetSymbolAddress((void**)&x1,   g_x1);
    cudaGetSymbolAddress((void**)&x2,   g_x2);
    cudaGetSymbolAddress((void**)&x3,   g_x3);
    cudaGetSymbolAddress((void**)&proj, g_proj);
    cudaGetSymbolAddress((void**)&skip, g_skip);
    cudaGetSymbolAddress((void**)&ssrc, g_ssrc);
    cudaGetSymbolAddress((void**)&stgt, g_stgt);
    cudaGetSymbolAddress((void**)&wtf,  g_wtf);

    uint32_t* W1t = wtf;
    uint32_t* S1t = wtf + 524288;
    uint32_t* W2t = wtf + 1048576;
    uint32_t* S2t = wtf + 1114112;

    // 3 stages: (A 128x36 + 2 * B 32x(BN+8)) words * 4B
    const int SMEM_L1 = 3 * (128 * 36 + 2 * 32 * 136) * 4;  // 159744
    const int SMEM_L2 = 3 * (128 * 36 + 2 * 32 * 72) * 4;   // 110592
    cudaFuncSetAttribute(gemm_dual_kernel<128>,
                         cudaFuncAttributeMaxDynamicSharedMemorySize, SMEM_L1);
    cudaFuncSetAttribute(gemm_dual_kernel<64>,
                         cudaFuncAttributeMaxDynamicSharedMemorySize, SMEM_L2);

    // ---- CSR build + weight conversion + layer0 score precompute ----
    zero_cnt_kernel<<<(NNODES + 255) / 256, 256>>>();
    count_kernel<<<(NEDGES + 255) / 256, 256>>>(tgt);
    scan_kernel<<<1, 1024>>>();
    scatter_kernel<<<(NEDGES + 255) / 256, 256>>>(src, tgt);
    conv_tf32_kernel<<<2048, 256>>>(W1, W1t, 524288);
    conv_tf32_kernel<<<2048, 256>>>(skip1, S1t, 524288);
    conv_tf32_kernel<<<256, 256>>>(W2, W2t, 65536);
    conv_tf32_kernel<<<256, 256>>>(skip2, S2t, 65536);
    precomp_c_kernel<<<1, 48>>>(W0, a_src0, a_tgt0);
    l0_scores_kernel<<<(NNODES * 8 + 255) / 256, 256>>>(fea);

    // ---- layer 0 fused agg ----
    agg0_kernel<<<NNODES, 512>>>(fea, W0, skip0, b0, x1);

    // ---- layer 1: nh=8, fo=128, concat, elu ----
    {
        gemm_dual_kernel<128><<<dim3(1024 / 128, NNODES / 128), 256, SMEM_L1>>>(
            (const uint32_t*)x1, W1t, S1t, proj, skip, NNODES, 512, 1024);
        int nh = 8, fo = 128;
        int nwarp = NNODES * nh;
        scores_kernel<<<(nwarp * 32 + 255) / 256, 256>>>(proj, a_src1, a_tgt1, ssrc, stgt, nh, fo);
        agg_kernel<<<dim3(NNODES, nh), fo>>>(proj, ssrc, stgt, skip, b1, x2, nh, fo, 1, 1);
    }

    // ---- layer 2: nh=1, fo=64, no act ----
    {
        gemm_dual_kernel<64><<<dim3(1, NNODES / 128), 256, SMEM_L2>>>(
            (const uint32_t*)x2, W2t, S2t, proj, skip, NNODES, 1024, 64);
        int nh = 1, fo = 64;
        int nwarp = NNODES * nh;
        scores_kernel<<<(nwarp * 32 + 255) / 256, 256>>>(proj, a_src2, a_tgt2, ssrc, stgt, nh, fo);
        agg_kernel<<<dim3(NNODES, nh), fo>>>(proj, ssrc, stgt, skip, b2, x3, nh, fo, 0, 0);
    }

    // ---- MLP head ----
    mlp_kernel<<<NCAND, 256>>>(x3, cand, mW1, mb1, mW2, mb2, mW3, mb3, (float*)d_out, out_size);
}

// round 6
// speedup vs baseline: 2.8393x; 1.1829x over previous
#include <cuda_runtime.h>
#include <math.h>
#include <stdint.h>

#define NNODES 16384
#define NEDGES 98304
#define NCAND  1024

// ---------------- scratch ----------------
__device__ float g_x1[NNODES * 512];     // layer0 output (tf32 bits)
__device__ float g_x2[NNODES * 1024];    // layer1 output (tf32 bits)
__device__ float g_x3[NNODES * 64];      // layer2 output (fp32)
__device__ float g_proj[NNODES * 1024];
__device__ float g_skip[NNODES * 1024];
__device__ float g_ssrc[NNODES * 8];
__device__ float g_stgt[NNODES * 8];
__device__ float g_alpha[NEDGES * 8];    // per-edge softmax weights (layer1)
__device__ int   g_cnt[NNODES];
__device__ int   g_off[NNODES + 1];
__device__ int   g_cur[NNODES];
__device__ int   g_srcs[NEDGES];
__device__ float g_csrc[24];             // layer0 folded a_src: [8 heads][3]
__device__ float g_ctgt[24];
__device__ float g_c1[8192];             // layer1 fold: c_src [8][512] then c_tgt [8][512]
// tf32 weights: W1(524288) skip1(524288) W2(65536) skip2(65536)
__device__ uint32_t g_wtf[1179648];

__device__ __forceinline__ uint32_t f2tf(float x) {
    uint32_t r;
    asm("cvt.rna.tf32.f32 %0, %1;" : "=r"(r) : "f"(x));
    return r;
}

// ---------------- CSR build ----------------
__global__ void zero_cnt_kernel() {
    int i = blockIdx.x * blockDim.x + threadIdx.x;
    if (i < NNODES) g_cnt[i] = 0;
}
__global__ void count_kernel(const int* __restrict__ tgt) {
    int e = blockIdx.x * blockDim.x + threadIdx.x;
    if (e < NEDGES) atomicAdd(&g_cnt[tgt[e]], 1);
}
__global__ void scan_kernel() {
    __shared__ int part[1024];
    const int PER = NNODES / 1024;
    int tid = threadIdx.x;
    int base = tid * PER;
    int local[PER];
    int s = 0;
#pragma unroll
    for (int i = 0; i < PER; i++) { local[i] = g_cnt[base + i]; s += local[i]; }
    part[tid] = s;
    __syncthreads();
    for (int d = 1; d < 1024; d <<= 1) {
        int v = (tid >= d) ? part[tid - d] : 0;
        __syncthreads();
        part[tid] += v;
        __syncthreads();
    }
    int run = (tid == 0) ? 0 : part[tid - 1];
#pragma unroll
    for (int i = 0; i < PER; i++) {
        g_off[base + i] = run;
        g_cur[base + i] = run;
        run += local[i];
    }
    if (tid == 1023) g_off[NNODES] = run;
}
__global__ void scatter_kernel(const int* __restrict__ src, const int* __restrict__ tgt) {
    int e = blockIdx.x * blockDim.x + threadIdx.x;
    if (e < NEDGES) {
        int p = atomicAdd(&g_cur[tgt[e]], 1);
        g_srcs[p] = src[e];
    }
}

// ---------------- weight tf32 conversion ----------------
__global__ void conv_tf32_kernel(const float* __restrict__ in, uint32_t* __restrict__ out, int n) {
    int i = blockIdx.x * blockDim.x + threadIdx.x;
    if (i < n) out[i] = f2tf(in[i]);
}

// ---------------- layer 0 folded score coefficients ----------------
__global__ void precomp_c_kernel(const float* __restrict__ W0,
                                 const float* __restrict__ a_src0,
                                 const float* __restrict__ a_tgt0) {
    int t = threadIdx.x;   // 48 threads
    int isT = t >= 24;
    int i = isT ? t - 24 : t;
    int h = i / 3, d = i % 3;
    const float* a = isT ? a_tgt0 : a_src0;
    float s = 0.f;
    for (int f = 0; f < 64; f++)
        s += W0[d * 512 + h * 64 + f] * a[h * 64 + f];
    (isT ? g_ctgt : g_csrc)[i] = s;
}

__global__ void l0_scores_kernel(const float* __restrict__ fea) {
    int i = blockIdx.x * blockDim.x + threadIdx.x;  // n*8+h
    if (i >= NNODES * 8) return;
    int n = i >> 3, h = i & 7;
    float f0 = fea[n * 3 + 0], f1 = fea[n * 3 + 1], f2 = fea[n * 3 + 2];
    g_ssrc[i] = f0 * g_csrc[h * 3] + f1 * g_csrc[h * 3 + 1] + f2 * g_csrc[h * 3 + 2];
    g_stgt[i] = f0 * g_ctgt[h * 3] + f1 * g_ctgt[h * 3 + 1] + f2 * g_ctgt[h * 3 + 2];
}

// ---------------- fused layer 0 agg ----------------
__global__ __launch_bounds__(512)
void agg0_kernel(const float* __restrict__ fea,
                 const float* __restrict__ W0, const float* __restrict__ S0,
                 const float* __restrict__ b0, float* __restrict__ out) {
    const int n = blockIdx.x;
    const int tid = threadIdx.x;
    const int warp = tid >> 5, lane = tid & 31;
    const int beg = g_off[n], end = g_off[n + 1];

    const float w0 = W0[tid], w1 = W0[512 + tid], w2 = W0[1024 + tid];
    const float s0 = S0[tid], s1 = S0[512 + tid], s2 = S0[1024 + tid];

    __shared__ float mh[8], ivh[8];
    __shared__ float al[32 * 8];
    __shared__ float sf[32 * 3];

    if (warp < 8) {
        const int h = warp;
        const float st = g_stgt[n * 8 + h];
        float m = -1e30f;
        for (int j = beg + lane; j < end; j += 32) {
            float e = g_ssrc[g_srcs[j] * 8 + h] + st;
            e = (e < 0.f) ? 0.2f * e : e;
            m = fmaxf(m, e);
        }
#pragma unroll
        for (int o = 16; o; o >>= 1) m = fmaxf(m, __shfl_xor_sync(0xffffffffu, m, o));
        float ss = 0.f;
        for (int j = beg + lane; j < end; j += 32) {
            float e = g_ssrc[g_srcs[j] * 8 + h] + st;
            e = (e < 0.f) ? 0.2f * e : e;
            ss += expf(e - m);
        }
#pragma unroll
        for (int o = 16; o; o >>= 1) ss += __shfl_xor_sync(0xffffffffu, ss, o);
        if (lane == 0) { mh[h] = m; ivh[h] = 1.f / (ss + 1e-16f); }
    }
    __syncthreads();

    const int myh = tid >> 6;
    float acc = 0.f;
    for (int j0 = beg; j0 < end; j0 += 32) {
        const int nj = min(32, end - j0);
        if (tid < 256) {
            const int l = tid & 31, h = tid >> 5;
            if (l < nj) {
                const int s = g_srcs[j0 + l];
                const float st = g_stgt[n * 8 + h];
                float e = g_ssrc[s * 8 + h] + st;
                e = (e < 0.f) ? 0.2f * e : e;
                al[l * 8 + h] = expf(e - mh[h]) * ivh[h];
                if (h == 0) {
                    sf[l * 3 + 0] = fea[s * 3 + 0];
                    sf[l * 3 + 1] = fea[s * 3 + 1];
                    sf[l * 3 + 2] = fea[s * 3 + 2];
                }
            }
        }
        __syncthreads();
        for (int l = 0; l < nj; l++) {
            const float a = al[l * 8 + myh];
            acc += a * (sf[l * 3] * w0 + sf[l * 3 + 1] * w1 + sf[l * 3 + 2] * w2);
        }
        __syncthreads();
    }

    const float f0 = fea[n * 3 + 0], f1 = fea[n * 3 + 1], f2 = fea[n * 3 + 2];
    float v = acc + (f0 * s0 + f1 * s1 + f2 * s2) + b0[tid];
    v = (v > 0.f) ? v : expm1f(v);
    out[n * 512 + tid] = __uint_as_float(f2tf(v));
}

// ---------------- layer 1 score folding ----------------
// c_src[h][k] = sum_f W1[k][h*128+f] * a_src1[h][f]   (stored [h*512+k])
__global__ void fold1_kernel(const float* __restrict__ W1,
                             const float* __restrict__ a_src1,
                             const float* __restrict__ a_tgt1) {
    int t = blockIdx.x * blockDim.x + threadIdx.x;   // 8192
    if (t >= 8192) return;
    int isT = t >= 4096;
    int i = t & 4095;
    int h = i >> 9, k = i & 511;
    const float* a = isT ? a_tgt1 : a_src1;
    float s = 0.f;
#pragma unroll 4
    for (int f = 0; f < 128; f++)
        s += W1[(size_t)k * 1024 + h * 128 + f] * a[h * 128 + f];
    g_c1[isT * 4096 + h * 512 + k] = s;
}

// s_src1[n,h] = sum_k x1[n,k] * c_src[h][k];  warp per 8 nodes
__global__ __launch_bounds__(256)
void scores1_kernel(const float* __restrict__ x1) {
    __shared__ float cs[4096], ct[4096];
    const int tid = threadIdx.x;
    for (int i = tid; i < 4096; i += 256) { cs[i] = g_c1[i]; ct[i] = g_c1[4096 + i]; }
    __syncthreads();
    const int warp = tid >> 5, lane = tid & 31;
    const int gw = blockIdx.x * 8 + warp;   // 0..2047
    for (int rep = 0; rep < 8; rep++) {
        const int n = gw * 8 + rep;
        float as[8] = {0, 0, 0, 0, 0, 0, 0, 0};
        float at[8] = {0, 0, 0, 0, 0, 0, 0, 0};
        for (int k = lane; k < 512; k += 32) {
            float v = x1[(size_t)n * 512 + k];
#pragma unroll
            for (int h = 0; h < 8; h++) {
                as[h] += v * cs[h * 512 + k];
                at[h] += v * ct[h * 512 + k];
            }
        }
#pragma unroll
        for (int h = 0; h < 8; h++) {
#pragma unroll
            for (int o = 16; o; o >>= 1) {
                as[h] += __shfl_xor_sync(0xffffffffu, as[h], o);
                at[h] += __shfl_xor_sync(0xffffffffu, at[h], o);
            }
        }
        if (lane < 8) {
            g_ssrc[n * 8 + lane] = as[lane];
            g_stgt[n * 8 + lane] = at[lane];
        }
    }
}

// ---------------- per-edge alpha for layer 1 (warp per node) ----------------
__global__ __launch_bounds__(256)
void alpha1_kernel() {
    const int warp = threadIdx.x >> 5, lane = threadIdx.x & 31;
    const int n = blockIdx.x * 8 + warp;
    const int beg = g_off[n], end = g_off[n + 1];
#pragma unroll
    for (int h = 0; h < 8; h++) {
        const float st = g_stgt[n * 8 + h];
        float m = -1e30f;
        for (int j = beg + lane; j < end; j += 32) {
            float e = g_ssrc[g_srcs[j] * 8 + h] + st;
            e = (e < 0.f) ? 0.2f * e : e;
            m = fmaxf(m, e);
        }
#pragma unroll
        for (int o = 16; o; o >>= 1) m = fmaxf(m, __shfl_xor_sync(0xffffffffu, m, o));
        float ss = 0.f;
        for (int j = beg + lane; j < end; j += 32) {
            float e = g_ssrc[g_srcs[j] * 8 + h] + st;
            e = (e < 0.f) ? 0.2f * e : e;
            ss += expf(e - m);
        }
#pragma unroll
        for (int o = 16; o; o >>= 1) ss += __shfl_xor_sync(0xffffffffu, ss, o);
        const float inv = 1.f / (ss + 1e-16f);
        for (int j = beg + lane; j < end; j += 32) {
            float e = g_ssrc[g_srcs[j] * 8 + h] + st;
            e = (e < 0.f) ? 0.2f * e : e;
            g_alpha[j * 8 + h] = expf(e - m) * inv;
        }
    }
}

// ---------------- single-pass layer-1 aggregate ----------------
// block = 512 threads per node; element e (of 1024) -> head e>>7
__global__ __launch_bounds__(512)
void agg1_kernel(const float* __restrict__ proj, const float* __restrict__ skip,
                 const float* __restrict__ bias, float* __restrict__ out) {
    const int n = blockIdx.x;
    const int tid = threadIdx.x;
    const int beg = g_off[n], end = g_off[n + 1];
    const int h0 = tid >> 7, h1 = (tid + 512) >> 7;
    float acc0 = 0.f, acc1 = 0.f;
    for (int j = beg; j < end; j++) {
        const int s = g_srcs[j];
        const float* p = proj + (size_t)s * 1024;
        acc0 += g_alpha[j * 8 + h0] * p[tid];
        acc1 += g_alpha[j * 8 + h1] * p[tid + 512];
    }
    const size_t base = (size_t)n * 1024;
    float v0 = acc0 + skip[base + tid] + bias[tid];
    float v1 = acc1 + skip[base + tid + 512] + bias[tid + 512];
    v0 = (v0 > 0.f) ? v0 : expm1f(v0);
    v1 = (v1 > 0.f) ? v1 : expm1f(v1);
    out[base + tid] = __uint_as_float(f2tf(v0));
    out[base + tid + 512] = __uint_as_float(f2tf(v1));
}

// ---------------- cp.async helpers ----------------
__device__ __forceinline__ void cp16(void* s, const void* g) {
    uint32_t sa = (uint32_t)__cvta_generic_to_shared(s);
    asm volatile("cp.async.cg.shared.global [%0], [%1], 16;\n" :: "r"(sa), "l"(g));
}
__device__ __forceinline__ void cp_commit() { asm volatile("cp.async.commit_group;\n"); }

// ---------------- dual-B TF32 tensor GEMM, 3-stage pipeline ----------------
template <int BN>
__global__ __launch_bounds__(256, 1)
void gemm_dual_kernel(const uint32_t* __restrict__ A,
                      const uint32_t* __restrict__ B0, const uint32_t* __restrict__ B1,
                      float* __restrict__ C0, float* __restrict__ C1,
                      int N, int K, int M) {
    constexpr int BM = 128, BK = 32;
    constexpr int SA = BK + 4;
    constexpr int SB = BN + 8;
    constexpr int WN = BN / 2;
    constexpr int NT = WN / 8;
    constexpr int AW = BM * SA;
    constexpr int BW = BK * SB;
    constexpr int STW = AW + 2 * BW;

    extern __shared__ uint32_t sm[];

    const int tid = threadIdx.x;
    const int warp = tid >> 5, lane = tid & 31;
    const int g = lane >> 2, tig = lane & 3;
    const int half = warp >> 2;
    const int wsub = warp & 3;
    const int wy = wsub >> 1, wx = wsub & 1;
    const int row0 = blockIdx.y * BM;
    const int col0 = blockIdx.x * BN;
    float* Cm = half ? C1 : C0;

    float acc[4][NT][4];
#pragma unroll
    for (int i = 0; i < 4; i++)
#pragma unroll
        for (int j = 0; j < NT; j++)
#pragma unroll
            for (int q = 0; q < 4; q++) acc[i][j][q] = 0.f;

    const int KT = K / BK;

    auto load_stage = [&](int s, int c) {
        const int k0 = c * BK;
        uint32_t* as = sm + s * STW;
#pragma unroll
        for (int it = 0; it < 4; it++) {
            int idx = tid + it * 256;
            int r = idx >> 3, q = idx & 7;
            cp16(&as[r * SA + q * 4], &A[(size_t)(row0 + r) * K + k0 + q * 4]);
        }
        uint32_t* bs0 = sm + s * STW + AW;
        uint32_t* bs1 = bs0 + BW;
        constexpr int QB = BK * BN / 4;
#pragma unroll
        for (int it = 0; it < QB / 256; it++) {
            int idx = tid + it * 256;
            int r = idx / (BN / 4), q = idx % (BN / 4);
            size_t go = (size_t)(k0 + r) * M + col0 + q * 4;
            cp16(&bs0[r * SB + q * 4], &B0[go]);
            cp16(&bs1[r * SB + q * 4], &B1[go]);
        }
        cp_commit();
    };

    load_stage(0, 0);
    load_stage(1, 1);

    for (int c = 0; c < KT; c++) {
        if (c + 2 < KT) {
            load_stage((c + 2) % 3, c + 2);
            asm volatile("cp.async.wait_group 2;\n");
        } else {
            asm volatile("cp.async.wait_group 0;\n");
        }
        __syncthreads();

        const uint32_t* as = sm + (c % 3) * STW;
        const uint32_t* bs = as + AW + half * BW;
#pragma unroll
        for (int kk = 0; kk < BK; kk += 8) {
            uint32_t a[4][4], b[NT][2];
#pragma unroll
            for (int mt = 0; mt < 4; mt++) {
                int br = wy * 64 + mt * 16;
                a[mt][0] = as[(br + g) * SA + kk + tig];
                a[mt][1] = as[(br + g + 8) * SA + kk + tig];
                a[mt][2] = as[(br + g) * SA + kk + tig + 4];
                a[mt][3] = as[(br + g + 8) * SA + kk + tig + 4];
            }
#pragma unroll
            for (int nt = 0; nt < NT; nt++) {
                int bc = wx * WN + nt * 8;
                b[nt][0] = bs[(kk + tig) * SB + bc + g];
                b[nt][1] = bs[(kk + tig + 4) * SB + bc + g];
            }
#pragma unroll
            for (int mt = 0; mt < 4; mt++)
#pragma unroll
                for (int nt = 0; nt < NT; nt++) {
                    asm volatile(
                        "mma.sync.aligned.m16n8k8.row.col.f32.tf32.tf32.f32 "
                        "{%0,%1,%2,%3}, {%4,%5,%6,%7}, {%8,%9}, {%0,%1,%2,%3};\n"
                        : "+f"(acc[mt][nt][0]), "+f"(acc[mt][nt][1]),
                          "+f"(acc[mt][nt][2]), "+f"(acc[mt][nt][3])
                        : "r"(a[mt][0]), "r"(a[mt][1]), "r"(a[mt][2]), "r"(a[mt][3]),
                          "r"(b[nt][0]), "r"(b[nt][1]));
                }
        }
        __syncthreads();
    }

#pragma unroll
    for (int mt = 0; mt < 4; mt++) {
#pragma unroll
        for (int nt = 0; nt < NT; nt++) {
            int r = row0 + wy * 64 + mt * 16 + g;
            int cc = col0 + wx * WN + nt * 8 + tig * 2;
            *reinterpret_cast<float2*>(&Cm[(size_t)r * M + cc]) =
                make_float2(acc[mt][nt][0], acc[mt][nt][1]);
            *reinterpret_cast<float2*>(&Cm[(size_t)(r + 8) * M + cc]) =
                make_float2(acc[mt][nt][2], acc[mt][nt][3]);
        }
    }
}

// ---------------- attention scores (layer 2) ----------------
__global__ void scores_kernel(const float* __restrict__ proj,
                              const float* __restrict__ a_src,
                              const float* __restrict__ a_tgt,
                              float* __restrict__ ssrc, float* __restrict__ stgt,
                              int nh, int fo) {
    int gw = (blockIdx.x * blockDim.x + threadIdx.x) >> 5;
    int lane = threadIdx.x & 31;
    int total = NNODES * nh;
    if (gw >= total) return;
    int n = gw / nh, h = gw % nh;
    const float* p = proj + (size_t)n * nh * fo + h * fo;
    float as_ = 0.f, at_ = 0.f;
    for (int f = lane; f < fo; f += 32) {
        float v = p[f];
        as_ += v * a_src[h * fo + f];
        at_ += v * a_tgt[h * fo + f];
    }
#pragma unroll
    for (int o = 16; o; o >>= 1) {
        as_ += __shfl_down_sync(0xffffffffu, as_, o);
        at_ += __shfl_down_sync(0xffffffffu, at_, o);
    }
    if (lane == 0) { ssrc[n * nh + h] = as_; stgt[n * nh + h] = at_; }
}

// ---------------- softmax-aggregate (layer 2) ----------------
__global__ void agg_kernel(const float* __restrict__ proj,
                           const float* __restrict__ ssrc,
                           const float* __restrict__ stgt,
                           const float* __restrict__ skip,
                           const float* __restrict__ bias,
                           float* __restrict__ out,
                           int nh, int fo, int act, int otf) {
    int n = blockIdx.x, h = blockIdx.y;
    int tid = threadIdx.x;
    int beg = g_off[n], end = g_off[n + 1];
    float st = stgt[n * nh + h];
    __shared__ float red[128];

    float m = -1e30f;
    for (int j = beg + tid; j < end; j += blockDim.x) {
        float e = ssrc[g_srcs[j] * nh + h] + st;
        e = (e < 0.f) ? 0.2f * e : e;
        m = fmaxf(m, e);
    }
    red[tid] = m;
    __syncthreads();
    for (int s = blockDim.x >> 1; s; s >>= 1) {
        if (tid < s) red[tid] = fmaxf(red[tid], red[tid + s]);
        __syncthreads();
    }
    m = red[0];
    __syncthreads();

    float ssum = 0.f;
    for (int j = beg + tid; j < end; j += blockDim.x) {
        float e = ssrc[g_srcs[j] * nh + h] + st;
        e = (e < 0.f) ? 0.2f * e : e;
        ssum += expf(e - m);
    }
    red[tid] = ssum;
    __syncthreads();
    for (int s = blockDim.x >> 1; s; s >>= 1) {
        if (tid < s) red[tid] += red[tid + s];
        __syncthreads();
    }
    float inv = 1.f / (red[0] + 1e-16f);
    __syncthreads();

    float acc = 0.f;
    for (int j = beg; j < end; j++) {
        int s_ = g_srcs[j];
        float e = ssrc[s_ * nh + h] + st;
        e = (e < 0.f) ? 0.2f * e : e;
        float alpha = expf(e - m) * inv;
        acc += alpha * proj[(size_t)s_ * nh * fo + h * fo + tid];
    }
    size_t idx = (size_t)n * nh * fo + h * fo + tid;
    float v = acc + skip[idx] + bias[h * fo + tid];
    if (act) v = (v > 0.f) ? v : expm1f(v);
    out[idx] = otf ? __uint_as_float(f2tf(v)) : v;
}

// ---------------- MLP head ----------------
__global__ void mlp_kernel(const float* __restrict__ x3, const int* __restrict__ cand,
                           const float* __restrict__ mW1, const float* __restrict__ mb1,
                           const float* __restrict__ mW2, const float* __restrict__ mb2,
                           const float* __restrict__ mW3, const float* __restrict__ mb3,
                           float* __restrict__ out, int out_size) {
    int c = blockIdx.x;
    int tid = threadIdx.x;
    __shared__ float sc[64];
    __shared__ float sh[256];
    int cid = cand[c];
    if (tid < 64) sc[tid] = x3[cid * 64 + tid];
    __syncthreads();

    float acc = mb1[tid];
#pragma unroll 8
    for (int k = 0; k < 64; k++) acc += sc[k] * mW1[k * 256 + tid];
    float h1 = tanhf(acc);
    sh[tid] = h1;
    __syncthreads();

    acc = mb2[tid];
#pragma unroll 8
    for (int k = 0; k < 256; k++) acc += sh[k] * mW2[k * 256 + tid];
    float h2 = tanhf(acc);
    __syncthreads();

    sh[tid] = h2 * mW3[tid];
    __syncthreads();
    for (int s = 128; s; s >>= 1) {
        if (tid < s) sh[tid] += sh[tid + s];
        __syncthreads();
    }
    if (tid == 0) out[c] = sh[0] + mb3[0];
    if (out_size > NCAND && tid == 1 && (NCAND + c) < out_size) {
        out[NCAND + c] = (float)cid;
    }
}

// ---------------- launch ----------------
extern "C" void kernel_launch(void* const* d_in, const int* in_sizes, int n_in,
                              void* d_out, int out_size) {
    const float* fea  = (const float*)d_in[0];
    const int*   ei   = (const int*)d_in[1];
    const int*   cand = (const int*)d_in[2];
    const float* W0 = (const float*)d_in[3];
    const float* a_src0 = (const float*)d_in[4];
    const float* a_tgt0 = (const float*)d_in[5];
    const float* b0 = (const float*)d_in[6];
    const float* skip0 = (const float*)d_in[7];
    const float* W1 = (const float*)d_in[8];
    const float* a_src1 = (const float*)d_in[9];
    const float* a_tgt1 = (const float*)d_in[10];
    const float* b1 = (const float*)d_in[11];
    const float* skip1 = (const float*)d_in[12];
    const float* W2 = (const float*)d_in[13];
    const float* a_src2 = (const float*)d_in[14];
    const float* a_tgt2 = (const float*)d_in[15];
    const float* b2 = (const float*)d_in[16];
    const float* skip2 = (const float*)d_in[17];
    const float* mW1 = (const float*)d_in[18];
    const float* mb1 = (const float*)d_in[19];
    const float* mW2 = (const float*)d_in[20];
    const float* mb2 = (const float*)d_in[21];
    const float* mW3 = (const float*)d_in[22];
    const float* mb3 = (const float*)d_in[23];

    const int E = in_sizes[1] / 2;
    const int* src = ei;
    const int* tgt = ei + E;

    float *x1, *x2, *x3, *proj, *skip, *ssrc, *stgt;
    uint32_t* wtf;
    cudaGetSymbolAddress((void**)&x1,   g_x1);
    cudaGetSymbolAddress((void**)&x2,   g_x2);
    cudaGetSymbolAddress((void**)&x3,   g_x3);
    cudaGetSymbolAddress((void**)&proj, g_proj);
    cudaGetSymbolAddress((void**)&skip, g_skip);
    cudaGetSymbolAddress((void**)&ssrc, g_ssrc);
    cudaGetSymbolAddress((void**)&stgt, g_stgt);
    cudaGetSymbolAddress((void**)&wtf,  g_wtf);

    uint32_t* W1t = wtf;
    uint32_t* S1t = wtf + 524288;
    uint32_t* W2t = wtf + 1048576;
    uint32_t* S2t = wtf + 1114112;

    const int SMEM_L1 = 3 * (128 * 36 + 2 * 32 * 136) * 4;  // 159744
    const int SMEM_L2 = 3 * (128 * 36 + 2 * 32 * 72) * 4;   // 110592
    cudaFuncSetAttribute(gemm_dual_kernel<128>,
                         cudaFuncAttributeMaxDynamicSharedMemorySize, SMEM_L1);
    cudaFuncSetAttribute(gemm_dual_kernel<64>,
                         cudaFuncAttributeMaxDynamicSharedMemorySize, SMEM_L2);

    // ---- CSR build + weight conversion + folds ----
    zero_cnt_kernel<<<(NNODES + 255) / 256, 256>>>();
    count_kernel<<<(NEDGES + 255) / 256, 256>>>(tgt);
    scan_kernel<<<1, 1024>>>();
    scatter_kernel<<<(NEDGES + 255) / 256, 256>>>(src, tgt);
    conv_tf32_kernel<<<2048, 256>>>(W1, W1t, 524288);
    conv_tf32_kernel<<<2048, 256>>>(skip1, S1t, 524288);
    conv_tf32_kernel<<<256, 256>>>(W2, W2t, 65536);
    conv_tf32_kernel<<<256, 256>>>(skip2, S2t, 65536);
    precomp_c_kernel<<<1, 48>>>(W0, a_src0, a_tgt0);
    fold1_kernel<<<32, 256>>>(W1, a_src1, a_tgt1);
    l0_scores_kernel<<<(NNODES * 8 + 255) / 256, 256>>>(fea);

    // ---- layer 0 fused agg ----
    agg0_kernel<<<NNODES, 512>>>(fea, W0, skip0, b0, x1);

    // ---- layer 1: nh=8, fo=128, concat, elu ----
    {
        // scores from x1 via fold (before GEMM; independent of proj)
        scores1_kernel<<<256, 256>>>(x1);
        alpha1_kernel<<<NNODES / 8, 256>>>();
        gemm_dual_kernel<128><<<dim3(1024 / 128, NNODES / 128), 256, SMEM_L1>>>(
            (const uint32_t*)x1, W1t, S1t, proj, skip, NNODES, 512, 1024);
        agg1_kernel<<<NNODES, 512>>>(proj, skip, b1, x2);
    }

    // ---- layer 2: nh=1, fo=64, no act ----
    {
        gemm_dual_kernel<64><<<dim3(1, NNODES / 128), 256, SMEM_L2>>>(
            (const uint32_t*)x2, W2t, S2t, proj, skip, NNODES, 1024, 64);
        int nh = 1, fo = 64;
        int nwarp = NNODES * nh;
        scores_kernel<<<(nwarp * 32 + 255) / 256, 256>>>(proj, a_src2, a_tgt2, ssrc, stgt, nh, fo);
        agg_kernel<<<dim3(NNODES, nh), fo>>>(proj, ssrc, stgt, skip, b2, x3, nh, fo, 0, 0);
    }

    // ---- MLP head ----
    mlp_kernel<<<NCAND, 256>>>(x3, cand, mW1, mb1, mW2, mb2, mW3, mb3, (float*)d_out, out_size);
}